// round 4
// baseline (speedup 1.0000x reference)
#include <cuda_runtime.h>

#define N_NODES 50000
#define E_EDGES 800000
#define K_DIM   128

// ---------------- scratch (allocation-free: __device__ globals) ----------------
__device__ __align__(16) int   g_is64;                  // edge_index dtype flag
__device__ __align__(16) int   g_cnt[N_NODES];          // in-degree (excl. self loop)
__device__ __align__(16) int   g_cur[N_NODES];          // fill cursor
__device__ __align__(16) int   g_off[N_NODES];          // CSR row offsets
__device__ __align__(16) float g_dis[N_NODES];          // deg^{-1/2} (incl. self loop)
__device__ __align__(16) int   g_csr_src[E_EDGES];      // CSR column (source node)
__device__ __align__(16) float g_csr_norm[E_EDGES];     // per-edge norm
__device__ __align__(16) float g_t1[(size_t)N_NODES * 128];  // X @ W1
__device__ __align__(16) float g_h [(size_t)N_NODES * 128];  // layer-1 output
__device__ __align__(16) float g_t2[(size_t)N_NODES * 64];   // h @ W2

// ---------------- dtype probe: int64 edge_index has zero odd words -------------
__global__ void detect_kernel(const int* __restrict__ ei32) {
    __shared__ int any_nz;
    if (threadIdx.x == 0) any_nz = 0;
    __syncthreads();
    // If data were int64 (values < 2^31), words at odd indices are all 0.
    int w = ei32[2 * threadIdx.x + 1];
    if (w != 0) atomicOr(&any_nz, 1);
    __syncthreads();
    if (threadIdx.x == 0) g_is64 = (any_nz == 0);
}

__device__ __forceinline__ int load_edge(const int* ei32, int row, int e, int is64) {
    int idx = row * E_EDGES + e;
    return is64 ? ei32[2 * idx] : ei32[idx];   // little-endian low word for int64
}

// ---------------- init: zero counters ------------------------------------------
__global__ void init_kernel() {
    int i = blockIdx.x * blockDim.x + threadIdx.x;
    if (i < N_NODES) { g_cnt[i] = 0; g_cur[i] = 0; }
}

// ---------------- histogram: in-degree by dst ----------------------------------
__global__ void count_kernel(const int* __restrict__ ei32) {
    int e = blockIdx.x * blockDim.x + threadIdx.x;
    if (e >= E_EDGES) return;
    int d = load_edge(ei32, 1, e, g_is64);
    atomicAdd(&g_cnt[d], 1);
}

// ---------------- one-block exclusive scan --------------------------------------
__global__ void scan_kernel() {
    __shared__ int sh[1024];
    const int CH = (N_NODES + 1023) / 1024;   // 49
    int t = threadIdx.x;
    int base = t * CH;
    int sum = 0;
    for (int i = 0; i < CH; i++) {
        int idx = base + i;
        if (idx < N_NODES) sum += g_cnt[idx];
    }
    sh[t] = sum;
    __syncthreads();
    for (int off = 1; off < 1024; off <<= 1) {
        int v = (t >= off) ? sh[t - off] : 0;
        __syncthreads();
        sh[t] += v;
        __syncthreads();
    }
    int run = sh[t] - sum;   // exclusive base for this chunk
    for (int i = 0; i < CH; i++) {
        int idx = base + i;
        if (idx < N_NODES) { g_off[idx] = run; run += g_cnt[idx]; }
    }
}

__global__ void dis_kernel() {
    int i = blockIdx.x * blockDim.x + threadIdx.x;
    if (i >= N_NODES) return;
    g_dis[i] = rsqrtf((float)(g_cnt[i] + 1));   // +1 self loop
}

// ---------------- CSR fill ------------------------------------------------------
__global__ void fill_kernel(const int* __restrict__ ei32) {
    int e = blockIdx.x * blockDim.x + threadIdx.x;
    if (e >= E_EDGES) return;
    int is64 = g_is64;
    int s = load_edge(ei32, 0, e, is64);
    int d = load_edge(ei32, 1, e, is64);
    int pos = g_off[d] + atomicAdd(&g_cur[d], 1);
    g_csr_src[pos]  = s;
    g_csr_norm[pos] = g_dis[s] * g_dis[d];
}

// ---------------- register-blocked SGEMM: T[N,BN] = X[N,128] @ W[128,BN] -------
template <int BN, int TM, int TN>
__global__ void gemm_kernel(const float* __restrict__ X, const float* __restrict__ W,
                            float* __restrict__ T, int N) {
    constexpr int BM = 64, BK = 16;
    constexpr int TX = BN / TN;
    constexpr int TY = BM / TM;
    static_assert(TX * TY == 256, "thread count");
    __shared__ float Xs[BK][BM + 4];
    __shared__ float Ws[BK][BN];

    int tid = threadIdx.x;
    int tx = tid % TX, ty = tid / TX;
    int row0 = blockIdx.x * BM;

    float acc[TM][TN];
#pragma unroll
    for (int i = 0; i < TM; i++)
#pragma unroll
        for (int j = 0; j < TN; j++) acc[i][j] = 0.f;

    for (int k0 = 0; k0 < K_DIM; k0 += BK) {
#pragma unroll
        for (int it = 0; it < (BM * BK) / 256; it++) {
            int p = tid + it * 256;
            int r = p / BK, kk = p % BK;
            int gr = row0 + r;
            Xs[kk][r] = (gr < N) ? X[(size_t)gr * K_DIM + k0 + kk] : 0.f;
        }
#pragma unroll
        for (int it = 0; it < (BK * BN) / 256; it++) {
            int p = tid + it * 256;
            int kk = p / BN, c = p % BN;
            Ws[kk][c] = W[(size_t)(k0 + kk) * BN + c];
        }
        __syncthreads();
#pragma unroll
        for (int kk = 0; kk < BK; kk++) {
            float xr[TM], wr[TN];
#pragma unroll
            for (int i = 0; i < TM; i++) xr[i] = Xs[kk][ty * TM + i];
#pragma unroll
            for (int j = 0; j < TN; j++) wr[j] = Ws[kk][tx * TN + j];
#pragma unroll
            for (int i = 0; i < TM; i++)
#pragma unroll
                for (int j = 0; j < TN; j++)
                    acc[i][j] += xr[i] * wr[j];
        }
        __syncthreads();
    }
#pragma unroll
    for (int i = 0; i < TM; i++) {
        int gr = row0 + ty * TM + i;
        if (gr < N) {
#pragma unroll
            for (int j = 0; j < TN; j++)
                T[(size_t)gr * BN + tx * TN + j] = acc[i][j];
        }
    }
}

// -------- aggregate layer 1: h = relu(sum_in(norm*t1[src]) + dis^2*t1[n] + b1) --
__global__ void agg1_kernel(const float* __restrict__ b1) {
    int warp = (blockIdx.x * blockDim.x + threadIdx.x) >> 5;
    int lane = threadIdx.x & 31;
    if (warp >= N_NODES) return;
    int beg = g_off[warp];
    int end = beg + g_cnt[warp];
    const float4* T = reinterpret_cast<const float4*>(g_t1);  // 32 float4 per row

    float4 acc = make_float4(0.f, 0.f, 0.f, 0.f);
    int j = beg;
    for (; j + 1 < end; j += 2) {
        int   s0 = g_csr_src[j],     s1 = g_csr_src[j + 1];
        float n0 = g_csr_norm[j],    n1 = g_csr_norm[j + 1];
        float4 v0 = T[(size_t)s0 * 32 + lane];
        float4 v1 = T[(size_t)s1 * 32 + lane];
        acc.x = fmaf(v0.x, n0, acc.x); acc.y = fmaf(v0.y, n0, acc.y);
        acc.z = fmaf(v0.z, n0, acc.z); acc.w = fmaf(v0.w, n0, acc.w);
        acc.x = fmaf(v1.x, n1, acc.x); acc.y = fmaf(v1.y, n1, acc.y);
        acc.z = fmaf(v1.z, n1, acc.z); acc.w = fmaf(v1.w, n1, acc.w);
    }
    if (j < end) {
        int   s0 = g_csr_src[j];
        float n0 = g_csr_norm[j];
        float4 v0 = T[(size_t)s0 * 32 + lane];
        acc.x = fmaf(v0.x, n0, acc.x); acc.y = fmaf(v0.y, n0, acc.y);
        acc.z = fmaf(v0.z, n0, acc.z); acc.w = fmaf(v0.w, n0, acc.w);
    }
    float ds = g_dis[warp];
    float sl = ds * ds;
    float4 t = T[(size_t)warp * 32 + lane];
    float4 b = reinterpret_cast<const float4*>(b1)[lane];
    float4 r;
    r.x = fmaxf(fmaf(t.x, sl, acc.x) + b.x, 0.f);
    r.y = fmaxf(fmaf(t.y, sl, acc.y) + b.y, 0.f);
    r.z = fmaxf(fmaf(t.z, sl, acc.z) + b.z, 0.f);
    r.w = fmaxf(fmaf(t.w, sl, acc.w) + b.w, 0.f);
    reinterpret_cast<float4*>(g_h)[(size_t)warp * 32 + lane] = r;
}

// -------- aggregate layer 2: out = sum_in(norm*t2[src]) + dis^2*t2[n] + b2 ------
__global__ void agg2_kernel(float* __restrict__ out, const float* __restrict__ b2) {
    int warp = (blockIdx.x * blockDim.x + threadIdx.x) >> 5;
    int lane = threadIdx.x & 31;
    if (warp >= N_NODES) return;
    int beg = g_off[warp];
    int end = beg + g_cnt[warp];
    const float2* T = reinterpret_cast<const float2*>(g_t2);  // 32 float2 per row

    float2 acc = make_float2(0.f, 0.f);
    int j = beg;
    for (; j + 1 < end; j += 2) {
        int   s0 = g_csr_src[j],     s1 = g_csr_src[j + 1];
        float n0 = g_csr_norm[j],    n1 = g_csr_norm[j + 1];
        float2 v0 = T[(size_t)s0 * 32 + lane];
        float2 v1 = T[(size_t)s1 * 32 + lane];
        acc.x = fmaf(v0.x, n0, acc.x); acc.y = fmaf(v0.y, n0, acc.y);
        acc.x = fmaf(v1.x, n1, acc.x); acc.y = fmaf(v1.y, n1, acc.y);
    }
    if (j < end) {
        int   s0 = g_csr_src[j];
        float n0 = g_csr_norm[j];
        float2 v0 = T[(size_t)s0 * 32 + lane];
        acc.x = fmaf(v0.x, n0, acc.x); acc.y = fmaf(v0.y, n0, acc.y);
    }
    float ds = g_dis[warp];
    float sl = ds * ds;
    float2 t = T[(size_t)warp * 32 + lane];
    float2 b = reinterpret_cast<const float2*>(b2)[lane];
    float2 r;
    r.x = fmaf(t.x, sl, acc.x) + b.x;
    r.y = fmaf(t.y, sl, acc.y) + b.y;
    reinterpret_cast<float2*>(out)[(size_t)warp * 32 + lane] = r;
}

// ---------------- launcher ----------------------------------------------------
extern "C" void kernel_launch(void* const* d_in, const int* in_sizes, int n_in,
                              void* d_out, int out_size) {
    const float* x  = (const float*)d_in[0];
    const int*   ei = (const int*)d_in[1];     // int32 (JAX default) or int64 (probed)
    const float* W1 = (const float*)d_in[2];
    const float* b1 = (const float*)d_in[3];
    const float* W2 = (const float*)d_in[4];
    const float* b2 = (const float*)d_in[5];
    float* out = (float*)d_out;
    (void)in_sizes; (void)n_in; (void)out_size;

    float *t1p, *hp, *t2p;
    cudaGetSymbolAddress((void**)&t1p, g_t1);
    cudaGetSymbolAddress((void**)&hp,  g_h);
    cudaGetSymbolAddress((void**)&t2p, g_t2);

    const int N = N_NODES, E = E_EDGES;

    // ---- CSR build ----
    detect_kernel<<<1, 256>>>(ei);
    init_kernel<<<(N + 255) / 256, 256>>>();
    count_kernel<<<(E + 255) / 256, 256>>>(ei);
    scan_kernel<<<1, 1024>>>();
    dis_kernel<<<(N + 255) / 256, 256>>>();
    fill_kernel<<<(E + 255) / 256, 256>>>(ei);

    // ---- Layer 1 ----
    gemm_kernel<128, 8, 4><<<(N + 63) / 64, 256>>>(x, W1, t1p, N);
    agg1_kernel<<<(N * 32 + 255) / 256, 256>>>(b1);   // 1 warp per node

    // ---- Layer 2 ----
    gemm_kernel<64, 4, 4><<<(N + 63) / 64, 256>>>(hp, W2, t2p, N);
    agg2_kernel<<<(N * 32 + 255) / 256, 256>>>(out, b2);
}

// round 5
// speedup vs baseline: 1.3511x; 1.3511x over previous
#include <cuda_runtime.h>

#define N_NODES 50000
#define E_EDGES 800000
#define K_DIM   128

// ---------------- scratch (allocation-free: __device__ globals) ----------------
__device__ __align__(16) int   g_is64;                  // edge_index dtype flag
__device__ __align__(16) int   g_total;                 // CSR allocator cursor
__device__ __align__(16) int   g_cnt[N_NODES];          // in-degree (excl. self loop)
__device__ __align__(16) int   g_cur[N_NODES];          // fill cursor
__device__ __align__(16) int   g_off[N_NODES];          // CSR row offsets
__device__ __align__(16) float g_dis[N_NODES];          // deg^{-1/2} (incl. self loop)
__device__ __align__(16) int   g_csr_src[E_EDGES];      // CSR column (source node)
__device__ __align__(16) float g_csr_norm[E_EDGES];     // per-edge norm
__device__ __align__(16) float g_t1[(size_t)N_NODES * 128];  // X @ W1
__device__ __align__(16) float g_h [(size_t)N_NODES * 128];  // layer-1 output
__device__ __align__(16) float g_t2[(size_t)N_NODES * 64];   // h @ W2

__device__ __forceinline__ int load_edge(const int* ei32, int row, int e, int is64) {
    int idx = row * E_EDGES + e;
    return is64 ? ei32[2 * idx] : ei32[idx];   // little-endian low word for int64
}

// ------------- init counters + detect edge dtype (block 0) ----------------------
__global__ void init_detect_kernel(const int* __restrict__ ei32) {
    int i = blockIdx.x * blockDim.x + threadIdx.x;
    if (i < N_NODES) { g_cnt[i] = 0; g_cur[i] = 0; }
    if (i == 0) g_total = 0;
    if (blockIdx.x == 0) {
        // int64 values < 2^31 have zero odd 32-bit words
        __shared__ int any_nz;
        if (threadIdx.x == 0) any_nz = 0;
        __syncthreads();
        if (ei32[2 * threadIdx.x + 1] != 0) atomicOr(&any_nz, 1);
        __syncthreads();
        if (threadIdx.x == 0) g_is64 = (any_nz == 0);
    }
}

// ---------------- histogram: in-degree by dst ----------------------------------
__global__ void count_kernel(const int* __restrict__ ei32) {
    int e = blockIdx.x * blockDim.x + threadIdx.x;
    if (e >= E_EDGES) return;
    int d = load_edge(ei32, 1, e, g_is64);
    atomicAdd(&g_cnt[d], 1);
}

// ------- offsets via warp-aggregated atomic allocator + dis ---------------------
__global__ void off_dis_kernel() {
    int i = blockIdx.x * blockDim.x + threadIdx.x;
    int lane = threadIdx.x & 31;
    int c = (i < N_NODES) ? g_cnt[i] : 0;
    // warp inclusive scan
    int pre = c;
#pragma unroll
    for (int o = 1; o < 32; o <<= 1) {
        int v = __shfl_up_sync(0xffffffffu, pre, o);
        if (lane >= o) pre += v;
    }
    int wsum = __shfl_sync(0xffffffffu, pre, 31);
    int base = 0;
    if (lane == 31 && wsum > 0) base = atomicAdd(&g_total, wsum);
    base = __shfl_sync(0xffffffffu, base, 31);
    if (i < N_NODES) {
        g_off[i] = base + pre - c;                 // exclusive prefix within warp
        g_dis[i] = rsqrtf((float)(c + 1));         // +1 self loop
    }
}

// ---------------- register-blocked SGEMM body ----------------------------------
template <int BN, int TM, int TN>
__device__ __forceinline__ void gemm_body(const float* __restrict__ X,
                                          const float* __restrict__ W,
                                          float* __restrict__ T, int N, int bx) {
    constexpr int BM = 64, BK = 16;
    constexpr int TX = BN / TN;
    constexpr int TY = BM / TM;
    static_assert(TX * TY == 256, "thread count");
    __shared__ float Xs[BK][BM + 4];
    __shared__ float Ws[BK][BN];

    int tid = threadIdx.x;
    int tx = tid % TX, ty = tid / TX;
    int row0 = bx * BM;

    float acc[TM][TN];
#pragma unroll
    for (int i = 0; i < TM; i++)
#pragma unroll
        for (int j = 0; j < TN; j++) acc[i][j] = 0.f;

    for (int k0 = 0; k0 < K_DIM; k0 += BK) {
#pragma unroll
        for (int it = 0; it < (BM * BK) / 256; it++) {
            int p = tid + it * 256;
            int r = p / BK, kk = p % BK;
            int gr = row0 + r;
            Xs[kk][r] = (gr < N) ? X[(size_t)gr * K_DIM + k0 + kk] : 0.f;
        }
#pragma unroll
        for (int it = 0; it < (BK * BN) / 256; it++) {
            int p = tid + it * 256;
            int kk = p / BN, c = p % BN;
            Ws[kk][c] = W[(size_t)(k0 + kk) * BN + c];
        }
        __syncthreads();
#pragma unroll
        for (int kk = 0; kk < BK; kk++) {
            float xr[TM], wr[TN];
#pragma unroll
            for (int i = 0; i < TM; i++) xr[i] = Xs[kk][ty * TM + i];
#pragma unroll
            for (int j = 0; j < TN; j++) wr[j] = Ws[kk][tx * TN + j];
#pragma unroll
            for (int i = 0; i < TM; i++)
#pragma unroll
                for (int j = 0; j < TN; j++)
                    acc[i][j] += xr[i] * wr[j];
        }
        __syncthreads();
    }
#pragma unroll
    for (int i = 0; i < TM; i++) {
        int gr = row0 + ty * TM + i;
        if (gr < N) {
#pragma unroll
            for (int j = 0; j < TN; j++)
                T[(size_t)gr * BN + tx * TN + j] = acc[i][j];
        }
    }
}

// ---------------- CSR fill body -------------------------------------------------
__device__ __forceinline__ void fill_body(const int* __restrict__ ei32, int b) {
    int e = b * 256 + threadIdx.x;
    if (e >= E_EDGES) return;
    int is64 = g_is64;
    int s = load_edge(ei32, 0, e, is64);
    int d = load_edge(ei32, 1, e, is64);
    int pos = g_off[d] + atomicAdd(&g_cur[d], 1);
    g_csr_src[pos]  = s;
    g_csr_norm[pos] = g_dis[s] * g_dis[d];
}

// --------- fused: GEMM1 (blocks [0,G1)) || CSR fill (blocks [G1,...)) -----------
#define G1_BLOCKS ((N_NODES + 63) / 64)
__global__ void gemm1_fill_kernel(const float* __restrict__ X,
                                  const float* __restrict__ W,
                                  const int* __restrict__ ei32) {
    if (blockIdx.x < G1_BLOCKS)
        gemm_body<128, 8, 4>(X, W, g_t1, N_NODES, blockIdx.x);
    else
        fill_body(ei32, blockIdx.x - G1_BLOCKS);
}

__global__ void gemm2_kernel(const float* __restrict__ X, const float* __restrict__ W,
                             float* __restrict__ T) {
    gemm_body<64, 4, 4>(X, W, T, N_NODES, blockIdx.x);
}

// -------- aggregate layer 1: h = relu(sum_in(norm*t1[src]) + dis^2*t1[n] + b1) --
__global__ void agg1_kernel(const float* __restrict__ b1) {
    int warp = (blockIdx.x * blockDim.x + threadIdx.x) >> 5;
    int lane = threadIdx.x & 31;
    if (warp >= N_NODES) return;
    int beg = g_off[warp];
    int end = beg + g_cnt[warp];
    const float4* T = reinterpret_cast<const float4*>(g_t1);  // 32 float4 per row

    float4 acc = make_float4(0.f, 0.f, 0.f, 0.f);
    int j = beg;
    for (; j + 3 < end; j += 4) {
        int   s0 = g_csr_src[j],   s1 = g_csr_src[j + 1];
        int   s2 = g_csr_src[j+2], s3 = g_csr_src[j + 3];
        float n0 = g_csr_norm[j],   n1 = g_csr_norm[j + 1];
        float n2 = g_csr_norm[j+2], n3 = g_csr_norm[j + 3];
        float4 v0 = T[(size_t)s0 * 32 + lane];
        float4 v1 = T[(size_t)s1 * 32 + lane];
        float4 v2 = T[(size_t)s2 * 32 + lane];
        float4 v3 = T[(size_t)s3 * 32 + lane];
        acc.x = fmaf(v0.x, n0, acc.x); acc.y = fmaf(v0.y, n0, acc.y);
        acc.z = fmaf(v0.z, n0, acc.z); acc.w = fmaf(v0.w, n0, acc.w);
        acc.x = fmaf(v1.x, n1, acc.x); acc.y = fmaf(v1.y, n1, acc.y);
        acc.z = fmaf(v1.z, n1, acc.z); acc.w = fmaf(v1.w, n1, acc.w);
        acc.x = fmaf(v2.x, n2, acc.x); acc.y = fmaf(v2.y, n2, acc.y);
        acc.z = fmaf(v2.z, n2, acc.z); acc.w = fmaf(v2.w, n2, acc.w);
        acc.x = fmaf(v3.x, n3, acc.x); acc.y = fmaf(v3.y, n3, acc.y);
        acc.z = fmaf(v3.z, n3, acc.z); acc.w = fmaf(v3.w, n3, acc.w);
    }
    for (; j < end; j++) {
        int   s0 = g_csr_src[j];
        float n0 = g_csr_norm[j];
        float4 v0 = T[(size_t)s0 * 32 + lane];
        acc.x = fmaf(v0.x, n0, acc.x); acc.y = fmaf(v0.y, n0, acc.y);
        acc.z = fmaf(v0.z, n0, acc.z); acc.w = fmaf(v0.w, n0, acc.w);
    }
    float ds = g_dis[warp];
    float sl = ds * ds;
    float4 t = T[(size_t)warp * 32 + lane];
    float4 b = reinterpret_cast<const float4*>(b1)[lane];
    float4 r;
    r.x = fmaxf(fmaf(t.x, sl, acc.x) + b.x, 0.f);
    r.y = fmaxf(fmaf(t.y, sl, acc.y) + b.y, 0.f);
    r.z = fmaxf(fmaf(t.z, sl, acc.z) + b.z, 0.f);
    r.w = fmaxf(fmaf(t.w, sl, acc.w) + b.w, 0.f);
    reinterpret_cast<float4*>(g_h)[(size_t)warp * 32 + lane] = r;
}

// -------- aggregate layer 2: out = sum_in(norm*t2[src]) + dis^2*t2[n] + b2 ------
__global__ void agg2_kernel(float* __restrict__ out, const float* __restrict__ b2) {
    int warp = (blockIdx.x * blockDim.x + threadIdx.x) >> 5;
    int lane = threadIdx.x & 31;
    if (warp >= N_NODES) return;
    int beg = g_off[warp];
    int end = beg + g_cnt[warp];
    const float2* T = reinterpret_cast<const float2*>(g_t2);  // 32 float2 per row

    float2 acc = make_float2(0.f, 0.f);
    int j = beg;
    for (; j + 3 < end; j += 4) {
        int   s0 = g_csr_src[j],   s1 = g_csr_src[j + 1];
        int   s2 = g_csr_src[j+2], s3 = g_csr_src[j + 3];
        float n0 = g_csr_norm[j],   n1 = g_csr_norm[j + 1];
        float n2 = g_csr_norm[j+2], n3 = g_csr_norm[j + 3];
        float2 v0 = T[(size_t)s0 * 32 + lane];
        float2 v1 = T[(size_t)s1 * 32 + lane];
        float2 v2 = T[(size_t)s2 * 32 + lane];
        float2 v3 = T[(size_t)s3 * 32 + lane];
        acc.x = fmaf(v0.x, n0, acc.x); acc.y = fmaf(v0.y, n0, acc.y);
        acc.x = fmaf(v1.x, n1, acc.x); acc.y = fmaf(v1.y, n1, acc.y);
        acc.x = fmaf(v2.x, n2, acc.x); acc.y = fmaf(v2.y, n2, acc.y);
        acc.x = fmaf(v3.x, n3, acc.x); acc.y = fmaf(v3.y, n3, acc.y);
    }
    for (; j < end; j++) {
        int   s0 = g_csr_src[j];
        float n0 = g_csr_norm[j];
        float2 v0 = T[(size_t)s0 * 32 + lane];
        acc.x = fmaf(v0.x, n0, acc.x); acc.y = fmaf(v0.y, n0, acc.y);
    }
    float ds = g_dis[warp];
    float sl = ds * ds;
    float2 t = T[(size_t)warp * 32 + lane];
    float2 b = reinterpret_cast<const float2*>(b2)[lane];
    float2 r;
    r.x = fmaf(t.x, sl, acc.x) + b.x;
    r.y = fmaf(t.y, sl, acc.y) + b.y;
    reinterpret_cast<float2*>(out)[(size_t)warp * 32 + lane] = r;
}

// ---------------- launcher ----------------------------------------------------
extern "C" void kernel_launch(void* const* d_in, const int* in_sizes, int n_in,
                              void* d_out, int out_size) {
    const float* x  = (const float*)d_in[0];
    const int*   ei = (const int*)d_in[1];     // int32 (JAX default) or int64 (probed)
    const float* W1 = (const float*)d_in[2];
    const float* b1 = (const float*)d_in[3];
    const float* W2 = (const float*)d_in[4];
    const float* b2 = (const float*)d_in[5];
    float* out = (float*)d_out;
    (void)in_sizes; (void)n_in; (void)out_size;

    float *hp, *t2p;
    cudaGetSymbolAddress((void**)&hp,  g_h);
    cudaGetSymbolAddress((void**)&t2p, g_t2);

    const int N = N_NODES, E = E_EDGES;

    // ---- CSR build ----
    init_detect_kernel<<<(N + 255) / 256, 256>>>(ei);
    count_kernel<<<(E + 255) / 256, 256>>>(ei);
    off_dis_kernel<<<(N + 255) / 256, 256>>>();

    // ---- Layer 1: GEMM1 overlapped with CSR fill in one grid ----
    {
        int grid = G1_BLOCKS + (E + 255) / 256;
        gemm1_fill_kernel<<<grid, 256>>>(x, W1, ei);
    }
    agg1_kernel<<<(N * 32 + 255) / 256, 256>>>(b1);   // 1 warp per node

    // ---- Layer 2 ----
    gemm2_kernel<<<(N + 63) / 64, 256>>>(hp, W2, t2p);
    agg2_kernel<<<(N * 32 + 255) / 256, 256>>>(out, b2);
}

// round 6
// speedup vs baseline: 1.6704x; 1.2363x over previous
#include <cuda_runtime.h>
#include <cstdint>

#define N_NODES 50000
#define E_EDGES 800000
#define K_DIM   128

// ---------------- scratch (allocation-free: __device__ globals) ----------------
__device__ __align__(16) int   g_is64;                  // edge_index dtype flag
__device__ __align__(16) int   g_total;                 // CSR allocator cursor
__device__ __align__(16) int   g_cnt[N_NODES];          // in-degree (excl. self loop)
__device__ __align__(16) int   g_cur[N_NODES];          // fill cursor
__device__ __align__(16) int   g_off[N_NODES];          // CSR row offsets
__device__ __align__(16) float g_dis[N_NODES];          // deg^{-1/2} (incl. self loop)
__device__ __align__(16) int   g_csr_src[E_EDGES];      // CSR column (source node)
__device__ __align__(16) float g_csr_norm[E_EDGES];     // per-edge norm
__device__ __align__(16) float g_t1[(size_t)N_NODES * 128];  // X @ W1
__device__ __align__(16) float g_h [(size_t)N_NODES * 128];  // layer-1 output
__device__ __align__(16) float g_t2[(size_t)N_NODES * 64];   // h @ W2

__device__ __forceinline__ int load_edge(const int* ei32, int row, int e, int is64) {
    int idx = row * E_EDGES + e;
    return is64 ? ei32[2 * idx] : ei32[idx];   // little-endian low word for int64
}

__device__ __forceinline__ uint32_t f2tf32(float f) {
    uint32_t u;
    asm("cvt.rna.tf32.f32 %0, %1;" : "=r"(u) : "f"(f));
    return u;
}

__device__ __forceinline__ void mma_tf32(float d[4],
                                         uint32_t a0, uint32_t a1, uint32_t a2, uint32_t a3,
                                         uint32_t b0, uint32_t b1) {
    asm volatile(
        "mma.sync.aligned.m16n8k8.row.col.f32.tf32.tf32.f32 "
        "{%0,%1,%2,%3}, {%4,%5,%6,%7}, {%8,%9}, {%0,%1,%2,%3};"
        : "+f"(d[0]), "+f"(d[1]), "+f"(d[2]), "+f"(d[3])
        : "r"(a0), "r"(a1), "r"(a2), "r"(a3), "r"(b0), "r"(b1));
}

// ------------- init counters + detect edge dtype (block 0) ----------------------
__global__ void init_detect_kernel(const int* __restrict__ ei32) {
    int i = blockIdx.x * blockDim.x + threadIdx.x;
    if (i < N_NODES) { g_cnt[i] = 0; g_cur[i] = 0; }
    if (i == 0) g_total = 0;
    if (blockIdx.x == 0) {
        __shared__ int any_nz;
        if (threadIdx.x == 0) any_nz = 0;
        __syncthreads();
        if (ei32[2 * threadIdx.x + 1] != 0) atomicOr(&any_nz, 1);
        __syncthreads();
        if (threadIdx.x == 0) g_is64 = (any_nz == 0);
    }
}

// ---------------- histogram: in-degree by dst ----------------------------------
__global__ void count_kernel(const int* __restrict__ ei32) {
    int e = blockIdx.x * blockDim.x + threadIdx.x;
    if (e >= E_EDGES) return;
    int d = load_edge(ei32, 1, e, g_is64);
    atomicAdd(&g_cnt[d], 1);
}

// ------- offsets via warp-aggregated atomic allocator + dis ---------------------
__global__ void off_dis_kernel() {
    int i = blockIdx.x * blockDim.x + threadIdx.x;
    int lane = threadIdx.x & 31;
    int c = (i < N_NODES) ? g_cnt[i] : 0;
    int pre = c;
#pragma unroll
    for (int o = 1; o < 32; o <<= 1) {
        int v = __shfl_up_sync(0xffffffffu, pre, o);
        if (lane >= o) pre += v;
    }
    int wsum = __shfl_sync(0xffffffffu, pre, 31);
    int base = 0;
    if (lane == 31 && wsum > 0) base = atomicAdd(&g_total, wsum);
    base = __shfl_sync(0xffffffffu, base, 31);
    if (i < N_NODES) {
        g_off[i] = base + pre - c;
        g_dis[i] = rsqrtf((float)(c + 1));
    }
}

// ---------------- tf32 tensor-core GEMM body ------------------------------------
// T[N,BN] = X[N,128] @ W[128,BN]; BM=128, BK=32; 256 threads = 8 warps.
template <int BN, int WARPS_M, int WARPS_N>
__device__ __forceinline__ void gemm_tf32_body(const float* __restrict__ X,
                                               const float* __restrict__ W,
                                               float* __restrict__ T, int N, int bx) {
    constexpr int BM = 128, BK = 32;
    constexpr int WM = BM / WARPS_M;       // warp tile rows
    constexpr int WN = BN / WARPS_N;       // warp tile cols
    constexpr int MT = WM / 16;            // m16 tiles per warp
    constexpr int NT = WN / 8;             // n8 tiles per warp
    constexpr int XPAD = 4, WPAD = 8;

    __shared__ uint32_t Xs[BM][BK + XPAD];
    __shared__ uint32_t Ws[BK][BN + WPAD];

    int tid  = threadIdx.x;
    int wid  = tid >> 5;
    int lane = tid & 31;
    int wm = wid / WARPS_N, wn = wid % WARPS_N;
    int warp_row = wm * WM;
    int warp_col = wn * WN;
    int row0 = bx * BM;
    int lr = lane >> 2;      // 0..7
    int lc = lane & 3;       // 0..3

    float d[MT][NT][4];
#pragma unroll
    for (int i = 0; i < MT; i++)
#pragma unroll
        for (int j = 0; j < NT; j++)
#pragma unroll
            for (int q = 0; q < 4; q++) d[i][j][q] = 0.f;

#pragma unroll
    for (int k0 = 0; k0 < K_DIM; k0 += BK) {
        // --- X tile: BM x BK floats = 1024 float4, 4 per thread
#pragma unroll
        for (int it = 0; it < 4; it++) {
            int f = tid + it * 256;
            int r = f >> 3, c4 = f & 7;
            int gr = row0 + r;
            float4 v = make_float4(0.f, 0.f, 0.f, 0.f);
            if (gr < N) v = *reinterpret_cast<const float4*>(&X[(size_t)gr * K_DIM + k0 + c4 * 4]);
            uint4 u = make_uint4(f2tf32(v.x), f2tf32(v.y), f2tf32(v.z), f2tf32(v.w));
            *reinterpret_cast<uint4*>(&Xs[r][c4 * 4]) = u;
        }
        // --- W tile: BK x BN floats
        constexpr int F4W = BN / 4;
#pragma unroll
        for (int it = 0; it < (BK * F4W) / 256; it++) {
            int f = tid + it * 256;
            int r = f / F4W, c4 = f % F4W;
            float4 v = *reinterpret_cast<const float4*>(&W[(size_t)(k0 + r) * BN + c4 * 4]);
            uint4 u = make_uint4(f2tf32(v.x), f2tf32(v.y), f2tf32(v.z), f2tf32(v.w));
            *reinterpret_cast<uint4*>(&Ws[r][c4 * 4]) = u;
        }
        __syncthreads();

#pragma unroll
        for (int kk = 0; kk < BK / 8; kk++) {
            uint32_t bf[NT][2];
#pragma unroll
            for (int nt = 0; nt < NT; nt++) {
                int col = warp_col + nt * 8 + lr;
                bf[nt][0] = Ws[kk * 8 + lc    ][col];
                bf[nt][1] = Ws[kk * 8 + lc + 4][col];
            }
#pragma unroll
            for (int mt = 0; mt < MT; mt++) {
                int rbase = warp_row + mt * 16 + lr;
                uint32_t a0 = Xs[rbase    ][kk * 8 + lc];
                uint32_t a1 = Xs[rbase + 8][kk * 8 + lc];
                uint32_t a2 = Xs[rbase    ][kk * 8 + lc + 4];
                uint32_t a3 = Xs[rbase + 8][kk * 8 + lc + 4];
#pragma unroll
                for (int nt = 0; nt < NT; nt++)
                    mma_tf32(d[mt][nt], a0, a1, a2, a3, bf[nt][0], bf[nt][1]);
            }
        }
        __syncthreads();
    }

    // --- store: per tile, (lr, 2lc)&(lr,2lc+1) and (+8 rows) as float2
#pragma unroll
    for (int mt = 0; mt < MT; mt++) {
#pragma unroll
        for (int nt = 0; nt < NT; nt++) {
            int r = row0 + warp_row + mt * 16 + lr;
            int c = warp_col + nt * 8 + 2 * lc;
            if (r < N)
                *reinterpret_cast<float2*>(&T[(size_t)r * BN + c]) =
                    make_float2(d[mt][nt][0], d[mt][nt][1]);
            if (r + 8 < N)
                *reinterpret_cast<float2*>(&T[(size_t)(r + 8) * BN + c]) =
                    make_float2(d[mt][nt][2], d[mt][nt][3]);
        }
    }
}

// ---------------- CSR fill body -------------------------------------------------
__device__ __forceinline__ void fill_body(const int* __restrict__ ei32, int b) {
    int e = b * 256 + threadIdx.x;
    if (e >= E_EDGES) return;
    int is64 = g_is64;
    int s = load_edge(ei32, 0, e, is64);
    int d = load_edge(ei32, 1, e, is64);
    int pos = g_off[d] + atomicAdd(&g_cur[d], 1);
    g_csr_src[pos]  = s;
    g_csr_norm[pos] = g_dis[s] * g_dis[d];
}

// --------- fused: GEMM1 (blocks [0,G1)) || CSR fill (blocks [G1,...)) -----------
#define G1_BLOCKS ((N_NODES + 127) / 128)
__global__ void gemm1_fill_kernel(const float* __restrict__ X,
                                  const float* __restrict__ W,
                                  const int* __restrict__ ei32) {
    if (blockIdx.x < G1_BLOCKS)
        gemm_tf32_body<128, 2, 4>(X, W, g_t1, N_NODES, blockIdx.x);
    else
        fill_body(ei32, blockIdx.x - G1_BLOCKS);
}

__global__ void gemm2_kernel(const float* __restrict__ X, const float* __restrict__ W,
                             float* __restrict__ T) {
    gemm_tf32_body<64, 4, 2>(X, W, T, N_NODES, blockIdx.x);
}

// -------- aggregate layer 1: h = relu(sum_in(norm*t1[src]) + dis^2*t1[n] + b1) --
__global__ void agg1_kernel(const float* __restrict__ b1) {
    int warp = (blockIdx.x * blockDim.x + threadIdx.x) >> 5;
    int lane = threadIdx.x & 31;
    if (warp >= N_NODES) return;
    int beg = g_off[warp];
    int end = beg + g_cnt[warp];
    const float4* T = reinterpret_cast<const float4*>(g_t1);  // 32 float4 per row

    float4 acc = make_float4(0.f, 0.f, 0.f, 0.f);
    int j = beg;
    for (; j + 3 < end; j += 4) {
        int   s0 = g_csr_src[j],   s1 = g_csr_src[j + 1];
        int   s2 = g_csr_src[j+2], s3 = g_csr_src[j + 3];
        float n0 = g_csr_norm[j],   n1 = g_csr_norm[j + 1];
        float n2 = g_csr_norm[j+2], n3 = g_csr_norm[j + 3];
        float4 v0 = T[(size_t)s0 * 32 + lane];
        float4 v1 = T[(size_t)s1 * 32 + lane];
        float4 v2 = T[(size_t)s2 * 32 + lane];
        float4 v3 = T[(size_t)s3 * 32 + lane];
        acc.x = fmaf(v0.x, n0, acc.x); acc.y = fmaf(v0.y, n0, acc.y);
        acc.z = fmaf(v0.z, n0, acc.z); acc.w = fmaf(v0.w, n0, acc.w);
        acc.x = fmaf(v1.x, n1, acc.x); acc.y = fmaf(v1.y, n1, acc.y);
        acc.z = fmaf(v1.z, n1, acc.z); acc.w = fmaf(v1.w, n1, acc.w);
        acc.x = fmaf(v2.x, n2, acc.x); acc.y = fmaf(v2.y, n2, acc.y);
        acc.z = fmaf(v2.z, n2, acc.z); acc.w = fmaf(v2.w, n2, acc.w);
        acc.x = fmaf(v3.x, n3, acc.x); acc.y = fmaf(v3.y, n3, acc.y);
        acc.z = fmaf(v3.z, n3, acc.z); acc.w = fmaf(v3.w, n3, acc.w);
    }
    for (; j < end; j++) {
        int   s0 = g_csr_src[j];
        float n0 = g_csr_norm[j];
        float4 v0 = T[(size_t)s0 * 32 + lane];
        acc.x = fmaf(v0.x, n0, acc.x); acc.y = fmaf(v0.y, n0, acc.y);
        acc.z = fmaf(v0.z, n0, acc.z); acc.w = fmaf(v0.w, n0, acc.w);
    }
    float ds = g_dis[warp];
    float sl = ds * ds;
    float4 t = T[(size_t)warp * 32 + lane];
    float4 b = reinterpret_cast<const float4*>(b1)[lane];
    float4 r;
    r.x = fmaxf(fmaf(t.x, sl, acc.x) + b.x, 0.f);
    r.y = fmaxf(fmaf(t.y, sl, acc.y) + b.y, 0.f);
    r.z = fmaxf(fmaf(t.z, sl, acc.z) + b.z, 0.f);
    r.w = fmaxf(fmaf(t.w, sl, acc.w) + b.w, 0.f);
    reinterpret_cast<float4*>(g_h)[(size_t)warp * 32 + lane] = r;
}

// -------- aggregate layer 2: out = sum_in(norm*t2[src]) + dis^2*t2[n] + b2 ------
__global__ void agg2_kernel(float* __restrict__ out, const float* __restrict__ b2) {
    int warp = (blockIdx.x * blockDim.x + threadIdx.x) >> 5;
    int lane = threadIdx.x & 31;
    if (warp >= N_NODES) return;
    int beg = g_off[warp];
    int end = beg + g_cnt[warp];
    const float2* T = reinterpret_cast<const float2*>(g_t2);  // 32 float2 per row

    float2 acc = make_float2(0.f, 0.f);
    int j = beg;
    for (; j + 3 < end; j += 4) {
        int   s0 = g_csr_src[j],   s1 = g_csr_src[j + 1];
        int   s2 = g_csr_src[j+2], s3 = g_csr_src[j + 3];
        float n0 = g_csr_norm[j],   n1 = g_csr_norm[j + 1];
        float n2 = g_csr_norm[j+2], n3 = g_csr_norm[j + 3];
        float2 v0 = T[(size_t)s0 * 32 + lane];
        float2 v1 = T[(size_t)s1 * 32 + lane];
        float2 v2 = T[(size_t)s2 * 32 + lane];
        float2 v3 = T[(size_t)s3 * 32 + lane];
        acc.x = fmaf(v0.x, n0, acc.x); acc.y = fmaf(v0.y, n0, acc.y);
        acc.x = fmaf(v1.x, n1, acc.x); acc.y = fmaf(v1.y, n1, acc.y);
        acc.x = fmaf(v2.x, n2, acc.x); acc.y = fmaf(v2.y, n2, acc.y);
        acc.x = fmaf(v3.x, n3, acc.x); acc.y = fmaf(v3.y, n3, acc.y);
    }
    for (; j < end; j++) {
        int   s0 = g_csr_src[j];
        float n0 = g_csr_norm[j];
        float2 v0 = T[(size_t)s0 * 32 + lane];
        acc.x = fmaf(v0.x, n0, acc.x); acc.y = fmaf(v0.y, n0, acc.y);
    }
    float ds = g_dis[warp];
    float sl = ds * ds;
    float2 t = T[(size_t)warp * 32 + lane];
    float2 b = reinterpret_cast<const float2*>(b2)[lane];
    float2 r;
    r.x = fmaf(t.x, sl, acc.x) + b.x;
    r.y = fmaf(t.y, sl, acc.y) + b.y;
    reinterpret_cast<float2*>(out)[(size_t)warp * 32 + lane] = r;
}

// ---------------- launcher ----------------------------------------------------
extern "C" void kernel_launch(void* const* d_in, const int* in_sizes, int n_in,
                              void* d_out, int out_size) {
    const float* x  = (const float*)d_in[0];
    const int*   ei = (const int*)d_in[1];     // int32 (JAX default) or int64 (probed)
    const float* W1 = (const float*)d_in[2];
    const float* b1 = (const float*)d_in[3];
    const float* W2 = (const float*)d_in[4];
    const float* b2 = (const float*)d_in[5];
    float* out = (float*)d_out;
    (void)in_sizes; (void)n_in; (void)out_size;

    float *hp, *t2p;
    cudaGetSymbolAddress((void**)&hp,  g_h);
    cudaGetSymbolAddress((void**)&t2p, g_t2);

    const int N = N_NODES, E = E_EDGES;

    // ---- CSR build ----
    init_detect_kernel<<<(N + 255) / 256, 256>>>(ei);
    count_kernel<<<(E + 255) / 256, 256>>>(ei);
    off_dis_kernel<<<(N + 255) / 256, 256>>>();

    // ---- Layer 1: tf32 GEMM1 overlapped with CSR fill in one grid ----
    {
        int grid = G1_BLOCKS + (E + 255) / 256;
        gemm1_fill_kernel<<<grid, 256>>>(x, W1, ei);
    }
    agg1_kernel<<<(N * 32 + 255) / 256, 256>>>(b1);   // 1 warp per node

    // ---- Layer 2 ----
    gemm2_kernel<<<G1_BLOCKS, 256>>>(hp, W2, t2p);
    agg2_kernel<<<(N * 32 + 255) / 256, 256>>>(out, b2);
}

// round 8
// speedup vs baseline: 1.7981x; 1.0764x over previous
#include <cuda_runtime.h>
#include <cstdint>

#define N_NODES 50000
#define E_EDGES 800000
#define K_DIM   128

// ---------------- scratch (allocation-free: __device__ globals) ----------------
__device__ __align__(16) int   g_is64;                  // edge_index dtype flag
__device__ __align__(16) int   g_total;                 // CSR allocator cursor
__device__ __align__(16) int   g_cnt[N_NODES];          // in-degree (excl. self loop)
__device__ __align__(16) int   g_cur[N_NODES];          // fill cursor
__device__ __align__(16) int   g_off[N_NODES];          // CSR row offsets
__device__ __align__(16) float g_dis[N_NODES];          // deg^{-1/2} (incl. self loop)
__device__ __align__(16) int   g_csr_src[E_EDGES];      // CSR column (source node)
__device__ __align__(16) float g_csr_norm[E_EDGES];     // per-edge norm
__device__ __align__(16) float g_t1[(size_t)N_NODES * 128];  // X @ W1
__device__ __align__(16) float g_h [(size_t)N_NODES * 128];  // layer-1 output
__device__ __align__(16) float g_t2[(size_t)N_NODES * 64];   // h @ W2

__device__ __forceinline__ int load_edge(const int* ei32, int row, int e, int is64) {
    int idx = row * E_EDGES + e;
    return is64 ? ei32[2 * idx] : ei32[idx];   // little-endian low word for int64
}

// ---------------- cp.async helpers ----------------------------------------------
__device__ __forceinline__ void cp_async16(void* smem, const void* gmem, int src_sz) {
    uint32_t s = (uint32_t)__cvta_generic_to_shared(smem);
    asm volatile("cp.async.cg.shared.global [%0], [%1], 16, %2;"
                 :: "r"(s), "l"(gmem), "r"(src_sz));
}

// rounded tf32 conversion (rna) — same numerics as the passing R6 kernel
__device__ __forceinline__ uint32_t f2tf32(float f) {
    uint32_t u;
    asm("cvt.rna.tf32.f32 %0, %1;" : "=r"(u) : "f"(f));
    return u;
}

__device__ __forceinline__ void mma_tf32(float d[4],
                                         uint32_t a0, uint32_t a1, uint32_t a2, uint32_t a3,
                                         uint32_t b0, uint32_t b1) {
    asm volatile(
        "mma.sync.aligned.m16n8k8.row.col.f32.tf32.tf32.f32 "
        "{%0,%1,%2,%3}, {%4,%5,%6,%7}, {%8,%9}, {%0,%1,%2,%3};"
        : "+f"(d[0]), "+f"(d[1]), "+f"(d[2]), "+f"(d[3])
        : "r"(a0), "r"(a1), "r"(a2), "r"(a3), "r"(b0), "r"(b1));
}

// ------------- init counters + detect edge dtype (block 0) ----------------------
__global__ void init_detect_kernel(const int* __restrict__ ei32) {
    int i = blockIdx.x * blockDim.x + threadIdx.x;
    if (i < N_NODES) { g_cnt[i] = 0; g_cur[i] = 0; }
    if (i == 0) g_total = 0;
    if (blockIdx.x == 0) {
        __shared__ int any_nz;
        if (threadIdx.x == 0) any_nz = 0;
        __syncthreads();
        if (ei32[2 * threadIdx.x + 1] != 0) atomicOr(&any_nz, 1);
        __syncthreads();
        if (threadIdx.x == 0) g_is64 = (any_nz == 0);
    }
}

// ---------------- histogram: in-degree by dst ----------------------------------
__global__ void count_kernel(const int* __restrict__ ei32) {
    int e = blockIdx.x * blockDim.x + threadIdx.x;
    if (e >= E_EDGES) return;
    int d = load_edge(ei32, 1, e, g_is64);
    atomicAdd(&g_cnt[d], 1);
}

// ------- offsets via warp-aggregated atomic allocator + dis ---------------------
__global__ void off_dis_kernel() {
    int i = blockIdx.x * blockDim.x + threadIdx.x;
    int lane = threadIdx.x & 31;
    int c = (i < N_NODES) ? g_cnt[i] : 0;
    int pre = c;
#pragma unroll
    for (int o = 1; o < 32; o <<= 1) {
        int v = __shfl_up_sync(0xffffffffu, pre, o);
        if (lane >= o) pre += v;
    }
    int wsum = __shfl_sync(0xffffffffu, pre, 31);
    int base = 0;
    if (lane == 31 && wsum > 0) base = atomicAdd(&g_total, wsum);
    base = __shfl_sync(0xffffffffu, base, 31);
    if (i < N_NODES) {
        g_off[i] = base + pre - c;
        g_dis[i] = rsqrtf((float)(c + 1));
    }
}

// ---------------- CSR fill (standalone, low-resource) ---------------------------
__global__ void fill_kernel(const int* __restrict__ ei32) {
    int e = blockIdx.x * blockDim.x + threadIdx.x;
    if (e >= E_EDGES) return;
    int is64 = g_is64;
    int s = load_edge(ei32, 0, e, is64);
    int d = load_edge(ei32, 1, e, is64);
    int pos = g_off[d] + atomicAdd(&g_cur[d], 1);
    g_csr_src[pos]  = s;
    g_csr_norm[pos] = g_dis[s] * g_dis[d];
}

// -------- tf32 GEMM, cp.async double-buffered: T[N,BN] = X[N,128] @ W[128,BN] ---
// Raw f32 in smem; cvt.rna.tf32 applied at register-load time (R6 numerics).
template <int BN, int WARPS_M, int WARPS_N>
__device__ __forceinline__ void gemm_db_body(const float* __restrict__ X,
                                             const float* __restrict__ W,
                                             float* __restrict__ T, int N, int bx) {
    constexpr int BM = 128, BK = 16, NK = K_DIM / BK;
    constexpr int THREADS = WARPS_M * WARPS_N * 32;
    constexpr int WM = BM / WARPS_M, WN = BN / WARPS_N;
    constexpr int MT = WM / 16, NT = WN / 8;
    constexpr int XST = BK + 4;   // padded row stride (floats)
    constexpr int WST = BN + 8;

    __shared__ float Xs[2][BM][XST];
    __shared__ float Ws[2][BK][WST];

    int tid  = threadIdx.x;
    int wid  = tid >> 5;
    int lane = tid & 31;
    int wm = wid / WARPS_N, wn = wid % WARPS_N;
    int warp_row = wm * WM;
    int warp_col = wn * WN;
    int row0 = bx * BM;
    int lr = lane >> 2;      // 0..7
    int lc = lane & 3;       // 0..3

    float d[MT][NT][4];
#pragma unroll
    for (int i = 0; i < MT; i++)
#pragma unroll
        for (int j = 0; j < NT; j++)
#pragma unroll
            for (int q = 0; q < 4; q++) d[i][j][q] = 0.f;

    auto load_stage = [&](int k0, int buf) {
#pragma unroll
        for (int f = tid; f < BM * BK / 4; f += THREADS) {
            int r = f / (BK / 4), c4 = f % (BK / 4);
            int gr = row0 + r;
            int grc = (gr < N) ? gr : (N - 1);    // safe address; size 0 if OOB
            cp_async16(&Xs[buf][r][c4 * 4],
                       &X[(size_t)grc * K_DIM + k0 + c4 * 4],
                       (gr < N) ? 16 : 0);
        }
#pragma unroll
        for (int f = tid; f < BK * BN / 4; f += THREADS) {
            int r = f / (BN / 4), c4 = f % (BN / 4);
            cp_async16(&Ws[buf][r][c4 * 4],
                       &W[(size_t)(k0 + r) * BN + c4 * 4], 16);
        }
        asm volatile("cp.async.commit_group;");
    };

    load_stage(0, 0);

#pragma unroll
    for (int k = 0; k < NK; k++) {
        if (k + 1 < NK) load_stage((k + 1) * BK, (k + 1) & 1);
        if (k + 1 < NK) asm volatile("cp.async.wait_group 1;");
        else            asm volatile("cp.async.wait_group 0;");
        __syncthreads();

        int buf = k & 1;
#pragma unroll
        for (int kk = 0; kk < BK / 8; kk++) {
            uint32_t bf[NT][2];
#pragma unroll
            for (int nt = 0; nt < NT; nt++) {
                int col = warp_col + nt * 8 + lr;
                bf[nt][0] = f2tf32(Ws[buf][kk * 8 + lc    ][col]);
                bf[nt][1] = f2tf32(Ws[buf][kk * 8 + lc + 4][col]);
            }
#pragma unroll
            for (int mt = 0; mt < MT; mt++) {
                int rbase = warp_row + mt * 16 + lr;
                uint32_t a0 = f2tf32(Xs[buf][rbase    ][kk * 8 + lc]);
                uint32_t a1 = f2tf32(Xs[buf][rbase + 8][kk * 8 + lc]);
                uint32_t a2 = f2tf32(Xs[buf][rbase    ][kk * 8 + lc + 4]);
                uint32_t a3 = f2tf32(Xs[buf][rbase + 8][kk * 8 + lc + 4]);
#pragma unroll
                for (int nt = 0; nt < NT; nt++)
                    mma_tf32(d[mt][nt], a0, a1, a2, a3, bf[nt][0], bf[nt][1]);
            }
        }
        __syncthreads();
    }

#pragma unroll
    for (int mt = 0; mt < MT; mt++) {
#pragma unroll
        for (int nt = 0; nt < NT; nt++) {
            int r = row0 + warp_row + mt * 16 + lr;
            int c = warp_col + nt * 8 + 2 * lc;
            if (r < N)
                *reinterpret_cast<float2*>(&T[(size_t)r * BN + c]) =
                    make_float2(d[mt][nt][0], d[mt][nt][1]);
            if (r + 8 < N)
                *reinterpret_cast<float2*>(&T[(size_t)(r + 8) * BN + c]) =
                    make_float2(d[mt][nt][2], d[mt][nt][3]);
        }
    }
}

__global__ void __launch_bounds__(512)
gemm1_kernel(const float* __restrict__ X, const float* __restrict__ W) {
    gemm_db_body<128, 4, 4>(X, W, g_t1, N_NODES, blockIdx.x);   // 16 warps, 32x32 tiles
}

__global__ void __launch_bounds__(256)
gemm2_kernel(const float* __restrict__ X, const float* __restrict__ W,
             float* __restrict__ T) {
    gemm_db_body<64, 4, 2>(X, W, T, N_NODES, blockIdx.x);       // 8 warps, 32x32 tiles
}

// -------- aggregate layer 1: h = relu(sum_in(norm*t1[src]) + dis^2*t1[n] + b1) --
__global__ void agg1_kernel(const float* __restrict__ b1) {
    int warp = (blockIdx.x * blockDim.x + threadIdx.x) >> 5;
    int lane = threadIdx.x & 31;
    if (warp >= N_NODES) return;
    int beg = g_off[warp];
    int end = beg + g_cnt[warp];
    const float4* T = reinterpret_cast<const float4*>(g_t1);  // 32 float4 per row

    float4 acc = make_float4(0.f, 0.f, 0.f, 0.f);
    int j = beg;
    for (; j + 3 < end; j += 4) {
        int   s0 = g_csr_src[j],   s1 = g_csr_src[j + 1];
        int   s2 = g_csr_src[j+2], s3 = g_csr_src[j + 3];
        float n0 = g_csr_norm[j],   n1 = g_csr_norm[j + 1];
        float n2 = g_csr_norm[j+2], n3 = g_csr_norm[j + 3];
        float4 v0 = T[(size_t)s0 * 32 + lane];
        float4 v1 = T[(size_t)s1 * 32 + lane];
        float4 v2 = T[(size_t)s2 * 32 + lane];
        float4 v3 = T[(size_t)s3 * 32 + lane];
        acc.x = fmaf(v0.x, n0, acc.x); acc.y = fmaf(v0.y, n0, acc.y);
        acc.z = fmaf(v0.z, n0, acc.z); acc.w = fmaf(v0.w, n0, acc.w);
        acc.x = fmaf(v1.x, n1, acc.x); acc.y = fmaf(v1.y, n1, acc.y);
        acc.z = fmaf(v1.z, n1, acc.z); acc.w = fmaf(v1.w, n1, acc.w);
        acc.x = fmaf(v2.x, n2, acc.x); acc.y = fmaf(v2.y, n2, acc.y);
        acc.z = fmaf(v2.z, n2, acc.z); acc.w = fmaf(v2.w, n2, acc.w);
        acc.x = fmaf(v3.x, n3, acc.x); acc.y = fmaf(v3.y, n3, acc.y);
        acc.z = fmaf(v3.z, n3, acc.z); acc.w = fmaf(v3.w, n3, acc.w);
    }
    for (; j < end; j++) {
        int   s0 = g_csr_src[j];
        float n0 = g_csr_norm[j];
        float4 v0 = T[(size_t)s0 * 32 + lane];
        acc.x = fmaf(v0.x, n0, acc.x); acc.y = fmaf(v0.y, n0, acc.y);
        acc.z = fmaf(v0.z, n0, acc.z); acc.w = fmaf(v0.w, n0, acc.w);
    }
    float ds = g_dis[warp];
    float sl = ds * ds;
    float4 t = T[(size_t)warp * 32 + lane];
    float4 b = reinterpret_cast<const float4*>(b1)[lane];
    float4 r;
    r.x = fmaxf(fmaf(t.x, sl, acc.x) + b.x, 0.f);
    r.y = fmaxf(fmaf(t.y, sl, acc.y) + b.y, 0.f);
    r.z = fmaxf(fmaf(t.z, sl, acc.z) + b.z, 0.f);
    r.w = fmaxf(fmaf(t.w, sl, acc.w) + b.w, 0.f);
    reinterpret_cast<float4*>(g_h)[(size_t)warp * 32 + lane] = r;
}

// -------- aggregate layer 2: out = sum_in(norm*t2[src]) + dis^2*t2[n] + b2 ------
__global__ void agg2_kernel(float* __restrict__ out, const float* __restrict__ b2) {
    int warp = (blockIdx.x * blockDim.x + threadIdx.x) >> 5;
    int lane = threadIdx.x & 31;
    if (warp >= N_NODES) return;
    int beg = g_off[warp];
    int end = beg + g_cnt[warp];
    const float2* T = reinterpret_cast<const float2*>(g_t2);  // 32 float2 per row

    float2 acc = make_float2(0.f, 0.f);
    int j = beg;
    for (; j + 3 < end; j += 4) {
        int   s0 = g_csr_src[j],   s1 = g_csr_src[j + 1];
        int   s2 = g_csr_src[j+2], s3 = g_csr_src[j + 3];
        float n0 = g_csr_norm[j],   n1 = g_csr_norm[j + 1];
        float n2 = g_csr_norm[j+2], n3 = g_csr_norm[j + 3];
        float2 v0 = T[(size_t)s0 * 32 + lane];
        float2 v1 = T[(size_t)s1 * 32 + lane];
        float2 v2 = T[(size_t)s2 * 32 + lane];
        float2 v3 = T[(size_t)s3 * 32 + lane];
        acc.x = fmaf(v0.x, n0, acc.x); acc.y = fmaf(v0.y, n0, acc.y);
        acc.x = fmaf(v1.x, n1, acc.x); acc.y = fmaf(v1.y, n1, acc.y);
        acc.x = fmaf(v2.x, n2, acc.x); acc.y = fmaf(v2.y, n2, acc.y);
        acc.x = fmaf(v3.x, n3, acc.x); acc.y = fmaf(v3.y, n3, acc.y);
    }
    for (; j < end; j++) {
        int   s0 = g_csr_src[j];
        float n0 = g_csr_norm[j];
        float2 v0 = T[(size_t)s0 * 32 + lane];
        acc.x = fmaf(v0.x, n0, acc.x); acc.y = fmaf(v0.y, n0, acc.y);
    }
    float ds = g_dis[warp];
    float sl = ds * ds;
    float2 t = T[(size_t)warp * 32 + lane];
    float2 b = reinterpret_cast<const float2*>(b2)[lane];
    float2 r;
    r.x = fmaf(t.x, sl, acc.x) + b.x;
    r.y = fmaf(t.y, sl, acc.y) + b.y;
    reinterpret_cast<float2*>(out)[(size_t)warp * 32 + lane] = r;
}

// ---------------- launcher ----------------------------------------------------
extern "C" void kernel_launch(void* const* d_in, const int* in_sizes, int n_in,
                              void* d_out, int out_size) {
    const float* x  = (const float*)d_in[0];
    const int*   ei = (const int*)d_in[1];     // int32 (JAX default) or int64 (probed)
    const float* W1 = (const float*)d_in[2];
    const float* b1 = (const float*)d_in[3];
    const float* W2 = (const float*)d_in[4];
    const float* b2 = (const float*)d_in[5];
    float* out = (float*)d_out;
    (void)in_sizes; (void)n_in; (void)out_size;

    float *hp, *t2p;
    cudaGetSymbolAddress((void**)&hp,  g_h);
    cudaGetSymbolAddress((void**)&t2p, g_t2);

    const int N = N_NODES, E = E_EDGES;
    const int GB = (N + 127) / 128;   // 391 GEMM blocks

    // ---- CSR build ----
    init_detect_kernel<<<(N + 255) / 256, 256>>>(ei);
    count_kernel<<<(E + 255) / 256, 256>>>(ei);
    off_dis_kernel<<<(N + 255) / 256, 256>>>();
    fill_kernel<<<(E + 255) / 256, 256>>>(ei);

    // ---- Layer 1 ----
    gemm1_kernel<<<GB, 512>>>(x, W1);
    agg1_kernel<<<(N * 32 + 255) / 256, 256>>>(b1);   // 1 warp per node

    // ---- Layer 2 ----
    gemm2_kernel<<<GB, 256>>>(hp, W2, t2p);
    agg2_kernel<<<(N * 32 + 255) / 256, 256>>>(out, b2);
}

// round 9
// speedup vs baseline: 1.9549x; 1.0872x over previous
#include <cuda_runtime.h>
#include <cstdint>

#define N_NODES 50000
#define E_EDGES 800000
#define K_DIM   128

// ---------------- scratch (allocation-free: __device__ globals) ----------------
__device__ __align__(16) int   g_is64;                  // edge_index dtype flag
__device__ __align__(16) int   g_total;                 // CSR allocator cursor
__device__ __align__(16) int   g_cnt[N_NODES];          // in-degree (excl. self loop)
__device__ __align__(16) int   g_off[N_NODES];          // CSR row offsets
__device__ __align__(16) float g_dis[N_NODES];          // deg^{-1/2} (incl. self loop)
__device__ __align__(16) int   g_rank[E_EDGES];         // edge rank within dst bucket
__device__ __align__(16) int   g_csr_src[E_EDGES];      // CSR column (source node)
__device__ __align__(16) float g_t1[(size_t)N_NODES * 128];  // dis * (X @ W1)
__device__ __align__(16) float g_h [(size_t)N_NODES * 128];  // layer-1 output
__device__ __align__(16) float g_t2[(size_t)N_NODES * 64];   // dis * (h @ W2)

__device__ __forceinline__ int load_edge(const int* ei32, int row, int e, int is64) {
    int idx = row * E_EDGES + e;
    return is64 ? ei32[2 * idx] : ei32[idx];   // little-endian low word for int64
}

// ---------------- cp.async helpers ----------------------------------------------
__device__ __forceinline__ void cp_async16(void* smem, const void* gmem, int src_sz) {
    uint32_t s = (uint32_t)__cvta_generic_to_shared(smem);
    asm volatile("cp.async.cg.shared.global [%0], [%1], 16, %2;"
                 :: "r"(s), "l"(gmem), "r"(src_sz));
}

// rounded tf32 conversion (rna)
__device__ __forceinline__ uint32_t f2tf32(float f) {
    uint32_t u;
    asm("cvt.rna.tf32.f32 %0, %1;" : "=r"(u) : "f"(f));
    return u;
}

__device__ __forceinline__ void mma_tf32(float d[4],
                                         uint32_t a0, uint32_t a1, uint32_t a2, uint32_t a3,
                                         uint32_t b0, uint32_t b1) {
    asm volatile(
        "mma.sync.aligned.m16n8k8.row.col.f32.tf32.tf32.f32 "
        "{%0,%1,%2,%3}, {%4,%5,%6,%7}, {%8,%9}, {%0,%1,%2,%3};"
        : "+f"(d[0]), "+f"(d[1]), "+f"(d[2]), "+f"(d[3])
        : "r"(a0), "r"(a1), "r"(a2), "r"(a3), "r"(b0), "r"(b1));
}

// ------------- init counters + detect edge dtype (block 0) ----------------------
__global__ void init_detect_kernel(const int* __restrict__ ei32) {
    int i = blockIdx.x * blockDim.x + threadIdx.x;
    if (i < N_NODES) g_cnt[i] = 0;
    if (i == 0) g_total = 0;
    if (blockIdx.x == 0) {
        __shared__ int any_nz;
        if (threadIdx.x == 0) any_nz = 0;
        __syncthreads();
        if (ei32[2 * threadIdx.x + 1] != 0) atomicOr(&any_nz, 1);
        __syncthreads();
        if (threadIdx.x == 0) g_is64 = (any_nz == 0);
    }
}

// -------- histogram: in-degree by dst; atomic return value = edge rank ----------
__global__ void count_kernel(const int* __restrict__ ei32) {
    int e = blockIdx.x * blockDim.x + threadIdx.x;
    if (e >= E_EDGES) return;
    int d = load_edge(ei32, 1, e, g_is64);
    g_rank[e] = atomicAdd(&g_cnt[d], 1);
}

// ------- offsets via warp-aggregated atomic allocator + dis ---------------------
__global__ void off_dis_kernel() {
    int i = blockIdx.x * blockDim.x + threadIdx.x;
    int lane = threadIdx.x & 31;
    int c = (i < N_NODES) ? g_cnt[i] : 0;
    int pre = c;
#pragma unroll
    for (int o = 1; o < 32; o <<= 1) {
        int v = __shfl_up_sync(0xffffffffu, pre, o);
        if (lane >= o) pre += v;
    }
    int wsum = __shfl_sync(0xffffffffu, pre, 31);
    int base = 0;
    if (lane == 31 && wsum > 0) base = atomicAdd(&g_total, wsum);
    base = __shfl_sync(0xffffffffu, base, 31);
    if (i < N_NODES) {
        g_off[i] = base + pre - c;
        g_dis[i] = rsqrtf((float)(c + 1));
    }
}

// ---------------- CSR fill: atomic-free (rank precomputed) ----------------------
__global__ void fill_kernel(const int* __restrict__ ei32) {
    int e = blockIdx.x * blockDim.x + threadIdx.x;
    if (e >= E_EDGES) return;
    int is64 = g_is64;
    int s = load_edge(ei32, 0, e, is64);
    int d = load_edge(ei32, 1, e, is64);
    g_csr_src[g_off[d] + g_rank[e]] = s;
}

// -------- tf32 GEMM, cp.async double-buffered, dis-prescaled output -------------
// T[r,:] = dis[r] * (X[r,:] @ W)  — the dis prescale folds the edge norm.
template <int BN, int WARPS_M, int WARPS_N>
__device__ __forceinline__ void gemm_db_body(const float* __restrict__ X,
                                             const float* __restrict__ W,
                                             float* __restrict__ T, int N, int bx) {
    constexpr int BM = 128, BK = 16, NK = K_DIM / BK;
    constexpr int THREADS = WARPS_M * WARPS_N * 32;
    constexpr int WM = BM / WARPS_M, WN = BN / WARPS_N;
    constexpr int MT = WM / 16, NT = WN / 8;
    constexpr int XST = BK + 4;   // padded row stride (floats)
    constexpr int WST = BN + 8;

    __shared__ float Xs[2][BM][XST];
    __shared__ float Ws[2][BK][WST];

    int tid  = threadIdx.x;
    int wid  = tid >> 5;
    int lane = tid & 31;
    int wm = wid / WARPS_N, wn = wid % WARPS_N;
    int warp_row = wm * WM;
    int warp_col = wn * WN;
    int row0 = bx * BM;
    int lr = lane >> 2;      // 0..7
    int lc = lane & 3;       // 0..3

    float d[MT][NT][4];
#pragma unroll
    for (int i = 0; i < MT; i++)
#pragma unroll
        for (int j = 0; j < NT; j++)
#pragma unroll
            for (int q = 0; q < 4; q++) d[i][j][q] = 0.f;

    auto load_stage = [&](int k0, int buf) {
#pragma unroll
        for (int f = tid; f < BM * BK / 4; f += THREADS) {
            int r = f / (BK / 4), c4 = f % (BK / 4);
            int gr = row0 + r;
            int grc = (gr < N) ? gr : (N - 1);    // safe address; size 0 if OOB
            cp_async16(&Xs[buf][r][c4 * 4],
                       &X[(size_t)grc * K_DIM + k0 + c4 * 4],
                       (gr < N) ? 16 : 0);
        }
#pragma unroll
        for (int f = tid; f < BK * BN / 4; f += THREADS) {
            int r = f / (BN / 4), c4 = f % (BN / 4);
            cp_async16(&Ws[buf][r][c4 * 4],
                       &W[(size_t)(k0 + r) * BN + c4 * 4], 16);
        }
        asm volatile("cp.async.commit_group;");
    };

    load_stage(0, 0);

#pragma unroll
    for (int k = 0; k < NK; k++) {
        if (k + 1 < NK) load_stage((k + 1) * BK, (k + 1) & 1);
        if (k + 1 < NK) asm volatile("cp.async.wait_group 1;");
        else            asm volatile("cp.async.wait_group 0;");
        __syncthreads();

        int buf = k & 1;
#pragma unroll
        for (int kk = 0; kk < BK / 8; kk++) {
            uint32_t bf[NT][2];
#pragma unroll
            for (int nt = 0; nt < NT; nt++) {
                int col = warp_col + nt * 8 + lr;
                bf[nt][0] = f2tf32(Ws[buf][kk * 8 + lc    ][col]);
                bf[nt][1] = f2tf32(Ws[buf][kk * 8 + lc + 4][col]);
            }
#pragma unroll
            for (int mt = 0; mt < MT; mt++) {
                int rbase = warp_row + mt * 16 + lr;
                uint32_t a0 = f2tf32(Xs[buf][rbase    ][kk * 8 + lc]);
                uint32_t a1 = f2tf32(Xs[buf][rbase + 8][kk * 8 + lc]);
                uint32_t a2 = f2tf32(Xs[buf][rbase    ][kk * 8 + lc + 4]);
                uint32_t a3 = f2tf32(Xs[buf][rbase + 8][kk * 8 + lc + 4]);
#pragma unroll
                for (int nt = 0; nt < NT; nt++)
                    mma_tf32(d[mt][nt], a0, a1, a2, a3, bf[nt][0], bf[nt][1]);
            }
        }
        __syncthreads();
    }

    // --- store, scaled by dis[row] (norm factorization) ---
#pragma unroll
    for (int mt = 0; mt < MT; mt++) {
        int r  = row0 + warp_row + mt * 16 + lr;
        float ds0 = (r < N)     ? g_dis[r]     : 0.f;
        float ds1 = (r + 8 < N) ? g_dis[r + 8] : 0.f;
#pragma unroll
        for (int nt = 0; nt < NT; nt++) {
            int c = warp_col + nt * 8 + 2 * lc;
            if (r < N)
                *reinterpret_cast<float2*>(&T[(size_t)r * BN + c]) =
                    make_float2(d[mt][nt][0] * ds0, d[mt][nt][1] * ds0);
            if (r + 8 < N)
                *reinterpret_cast<float2*>(&T[(size_t)(r + 8) * BN + c]) =
                    make_float2(d[mt][nt][2] * ds1, d[mt][nt][3] * ds1);
        }
    }
}

__global__ void __launch_bounds__(512)
gemm1_kernel(const float* __restrict__ X, const float* __restrict__ W) {
    gemm_db_body<128, 4, 4>(X, W, g_t1, N_NODES, blockIdx.x);   // 16 warps, 32x32 tiles
}

__global__ void __launch_bounds__(256)
gemm2_kernel(const float* __restrict__ X, const float* __restrict__ W,
             float* __restrict__ T) {
    gemm_db_body<64, 4, 2>(X, W, T, N_NODES, blockIdx.x);       // 8 warps, 32x32 tiles
}

// -------- aggregate layer 1: h = relu(dis[d]*(sum t1'[src] + t1'[d]) + b1) ------
__global__ void agg1_kernel(const float* __restrict__ b1) {
    int warp = (blockIdx.x * blockDim.x + threadIdx.x) >> 5;
    int lane = threadIdx.x & 31;
    if (warp >= N_NODES) return;
    int beg = g_off[warp];
    int end = beg + g_cnt[warp];
    const float4* T = reinterpret_cast<const float4*>(g_t1);  // 32 float4 per row

    float4 acc = make_float4(0.f, 0.f, 0.f, 0.f);
    int j = beg;
    for (; j + 3 < end; j += 4) {
        int s0 = g_csr_src[j],     s1 = g_csr_src[j + 1];
        int s2 = g_csr_src[j + 2], s3 = g_csr_src[j + 3];
        float4 v0 = T[(size_t)s0 * 32 + lane];
        float4 v1 = T[(size_t)s1 * 32 + lane];
        float4 v2 = T[(size_t)s2 * 32 + lane];
        float4 v3 = T[(size_t)s3 * 32 + lane];
        acc.x += v0.x + v1.x + v2.x + v3.x;
        acc.y += v0.y + v1.y + v2.y + v3.y;
        acc.z += v0.z + v1.z + v2.z + v3.z;
        acc.w += v0.w + v1.w + v2.w + v3.w;
    }
    for (; j < end; j++) {
        int s0 = g_csr_src[j];
        float4 v0 = T[(size_t)s0 * 32 + lane];
        acc.x += v0.x; acc.y += v0.y; acc.z += v0.z; acc.w += v0.w;
    }
    float ds = g_dis[warp];
    float4 t = T[(size_t)warp * 32 + lane];   // t1' self term (already dis-scaled)
    float4 b = reinterpret_cast<const float4*>(b1)[lane];
    float4 r;
    r.x = fmaxf(fmaf(acc.x + t.x, ds, b.x), 0.f);
    r.y = fmaxf(fmaf(acc.y + t.y, ds, b.y), 0.f);
    r.z = fmaxf(fmaf(acc.z + t.z, ds, b.z), 0.f);
    r.w = fmaxf(fmaf(acc.w + t.w, ds, b.w), 0.f);
    reinterpret_cast<float4*>(g_h)[(size_t)warp * 32 + lane] = r;
}

// -------- aggregate layer 2: out = dis[d]*(sum t2'[src] + t2'[d]) + b2 ----------
__global__ void agg2_kernel(float* __restrict__ out, const float* __restrict__ b2) {
    int warp = (blockIdx.x * blockDim.x + threadIdx.x) >> 5;
    int lane = threadIdx.x & 31;
    if (warp >= N_NODES) return;
    int beg = g_off[warp];
    int end = beg + g_cnt[warp];
    const float2* T = reinterpret_cast<const float2*>(g_t2);  // 32 float2 per row

    float2 acc = make_float2(0.f, 0.f);
    int j = beg;
    for (; j + 3 < end; j += 4) {
        int s0 = g_csr_src[j],     s1 = g_csr_src[j + 1];
        int s2 = g_csr_src[j + 2], s3 = g_csr_src[j + 3];
        float2 v0 = T[(size_t)s0 * 32 + lane];
        float2 v1 = T[(size_t)s1 * 32 + lane];
        float2 v2 = T[(size_t)s2 * 32 + lane];
        float2 v3 = T[(size_t)s3 * 32 + lane];
        acc.x += v0.x + v1.x + v2.x + v3.x;
        acc.y += v0.y + v1.y + v2.y + v3.y;
    }
    for (; j < end; j++) {
        int s0 = g_csr_src[j];
        float2 v0 = T[(size_t)s0 * 32 + lane];
        acc.x += v0.x; acc.y += v0.y;
    }
    float ds = g_dis[warp];
    float2 t = T[(size_t)warp * 32 + lane];   // t2' self term
    float2 b = reinterpret_cast<const float2*>(b2)[lane];
    float2 r;
    r.x = fmaf(acc.x + t.x, ds, b.x);
    r.y = fmaf(acc.y + t.y, ds, b.y);
    reinterpret_cast<float2*>(out)[(size_t)warp * 32 + lane] = r;
}

// ---------------- launcher ----------------------------------------------------
extern "C" void kernel_launch(void* const* d_in, const int* in_sizes, int n_in,
                              void* d_out, int out_size) {
    const float* x  = (const float*)d_in[0];
    const int*   ei = (const int*)d_in[1];     // int32 (JAX default) or int64 (probed)
    const float* W1 = (const float*)d_in[2];
    const float* b1 = (const float*)d_in[3];
    const float* W2 = (const float*)d_in[4];
    const float* b2 = (const float*)d_in[5];
    float* out = (float*)d_out;
    (void)in_sizes; (void)n_in; (void)out_size;

    float *hp, *t2p;
    cudaGetSymbolAddress((void**)&hp,  g_h);
    cudaGetSymbolAddress((void**)&t2p, g_t2);

    const int N = N_NODES, E = E_EDGES;
    const int GB = (N + 127) / 128;   // 391 GEMM blocks

    // ---- CSR build ----
    init_detect_kernel<<<(N + 255) / 256, 256>>>(ei);
    count_kernel<<<(E + 255) / 256, 256>>>(ei);
    off_dis_kernel<<<(N + 255) / 256, 256>>>();
    fill_kernel<<<(E + 255) / 256, 256>>>(ei);

    // ---- Layer 1 ----
    gemm1_kernel<<<GB, 512>>>(x, W1);
    agg1_kernel<<<(N * 32 + 255) / 256, 256>>>(b1);   // 1 warp per node

    // ---- Layer 2 ----
    gemm2_kernel<<<GB, 256>>>(hp, W2, t2p);
    agg2_kernel<<<(N * 32 + 255) / 256, 256>>>(out, b2);
}

// round 10
// speedup vs baseline: 2.1583x; 1.1040x over previous
#include <cuda_runtime.h>
#include <cuda_fp16.h>
#include <cstdint>

#define N_NODES 50000
#define E_EDGES 800000
#define K_DIM   128

// ---------------- scratch (allocation-free: __device__ globals) ----------------
__device__ __align__(16) int    g_is64;                 // edge_index dtype flag
__device__ __align__(16) int    g_total;                // CSR allocator cursor
__device__ __align__(16) int    g_cnt[N_NODES];         // in-degree (excl. self loop)
__device__ __align__(16) int    g_off[N_NODES];         // CSR row offsets
__device__ __align__(16) float  g_dis[N_NODES];         // deg^{-1/2} (incl. self loop)
__device__ __align__(16) int    g_rank[E_EDGES];        // edge rank within dst bucket
__device__ __align__(16) int    g_csr_src[E_EDGES];     // CSR column (source node)
__device__ __align__(16) __half g_t1[(size_t)N_NODES * 128]; // dis * (X @ W1), fp16
__device__ __align__(16) float  g_h [(size_t)N_NODES * 128]; // layer-1 output (fp32)
__device__ __align__(16) __half g_t2[(size_t)N_NODES * 64];  // dis * (h @ W2), fp16

__device__ __forceinline__ int load_edge(const int* ei32, int row, int e, int is64) {
    int idx = row * E_EDGES + e;
    return is64 ? ei32[2 * idx] : ei32[idx];   // little-endian low word for int64
}

// ---------------- cp.async helpers ----------------------------------------------
__device__ __forceinline__ void cp_async16(void* smem, const void* gmem, int src_sz) {
    uint32_t s = (uint32_t)__cvta_generic_to_shared(smem);
    asm volatile("cp.async.cg.shared.global [%0], [%1], 16, %2;"
                 :: "r"(s), "l"(gmem), "r"(src_sz));
}

// rounded tf32 conversion (rna)
__device__ __forceinline__ uint32_t f2tf32(float f) {
    uint32_t u;
    asm("cvt.rna.tf32.f32 %0, %1;" : "=r"(u) : "f"(f));
    return u;
}

__device__ __forceinline__ void mma_tf32(float d[4],
                                         uint32_t a0, uint32_t a1, uint32_t a2, uint32_t a3,
                                         uint32_t b0, uint32_t b1) {
    asm volatile(
        "mma.sync.aligned.m16n8k8.row.col.f32.tf32.tf32.f32 "
        "{%0,%1,%2,%3}, {%4,%5,%6,%7}, {%8,%9}, {%0,%1,%2,%3};"
        : "+f"(d[0]), "+f"(d[1]), "+f"(d[2]), "+f"(d[3])
        : "r"(a0), "r"(a1), "r"(a2), "r"(a3), "r"(b0), "r"(b1));
}

// ------------- init counters + detect edge dtype (block 0) ----------------------
__global__ void init_detect_kernel(const int* __restrict__ ei32) {
    int i = blockIdx.x * blockDim.x + threadIdx.x;
    if (i < N_NODES) g_cnt[i] = 0;
    if (i == 0) g_total = 0;
    if (blockIdx.x == 0) {
        __shared__ int any_nz;
        if (threadIdx.x == 0) any_nz = 0;
        __syncthreads();
        if (ei32[2 * threadIdx.x + 1] != 0) atomicOr(&any_nz, 1);
        __syncthreads();
        if (threadIdx.x == 0) g_is64 = (any_nz == 0);
    }
}

// -------- histogram: in-degree by dst; atomic return value = edge rank ----------
__global__ void count_kernel(const int* __restrict__ ei32) {
    int e = blockIdx.x * blockDim.x + threadIdx.x;
    if (e >= E_EDGES) return;
    int d = load_edge(ei32, 1, e, g_is64);
    g_rank[e] = atomicAdd(&g_cnt[d], 1);
}

// ------- offsets via warp-aggregated atomic allocator + dis ---------------------
__global__ void off_dis_kernel() {
    int i = blockIdx.x * blockDim.x + threadIdx.x;
    int lane = threadIdx.x & 31;
    int c = (i < N_NODES) ? g_cnt[i] : 0;
    int pre = c;
#pragma unroll
    for (int o = 1; o < 32; o <<= 1) {
        int v = __shfl_up_sync(0xffffffffu, pre, o);
        if (lane >= o) pre += v;
    }
    int wsum = __shfl_sync(0xffffffffu, pre, 31);
    int base = 0;
    if (lane == 31 && wsum > 0) base = atomicAdd(&g_total, wsum);
    base = __shfl_sync(0xffffffffu, base, 31);
    if (i < N_NODES) {
        g_off[i] = base + pre - c;
        g_dis[i] = rsqrtf((float)(c + 1));
    }
}

// ---------------- CSR fill: atomic-free (rank precomputed) ----------------------
__global__ void fill_kernel(const int* __restrict__ ei32) {
    int e = blockIdx.x * blockDim.x + threadIdx.x;
    if (e >= E_EDGES) return;
    int is64 = g_is64;
    int s = load_edge(ei32, 0, e, is64);
    int d = load_edge(ei32, 1, e, is64);
    g_csr_src[g_off[d] + g_rank[e]] = s;
}

// -------- tf32 GEMM, cp.async double-buffered, dis-prescaled fp16 output --------
// T[r,:] = half( dis[r] * (X[r,:] @ W) )
template <int BN, int WARPS_M, int WARPS_N>
__device__ __forceinline__ void gemm_db_body(const float* __restrict__ X,
                                             const float* __restrict__ W,
                                             __half* __restrict__ T, int N, int bx) {
    constexpr int BM = 128, BK = 16, NK = K_DIM / BK;
    constexpr int THREADS = WARPS_M * WARPS_N * 32;
    constexpr int WM = BM / WARPS_M, WN = BN / WARPS_N;
    constexpr int MT = WM / 16, NT = WN / 8;
    constexpr int XST = BK + 4;   // padded row stride (floats)
    constexpr int WST = BN + 8;

    __shared__ float Xs[2][BM][XST];
    __shared__ float Ws[2][BK][WST];

    int tid  = threadIdx.x;
    int wid  = tid >> 5;
    int lane = tid & 31;
    int wm = wid / WARPS_N, wn = wid % WARPS_N;
    int warp_row = wm * WM;
    int warp_col = wn * WN;
    int row0 = bx * BM;
    int lr = lane >> 2;      // 0..7
    int lc = lane & 3;       // 0..3

    float d[MT][NT][4];
#pragma unroll
    for (int i = 0; i < MT; i++)
#pragma unroll
        for (int j = 0; j < NT; j++)
#pragma unroll
            for (int q = 0; q < 4; q++) d[i][j][q] = 0.f;

    auto load_stage = [&](int k0, int buf) {
#pragma unroll
        for (int f = tid; f < BM * BK / 4; f += THREADS) {
            int r = f / (BK / 4), c4 = f % (BK / 4);
            int gr = row0 + r;
            int grc = (gr < N) ? gr : (N - 1);    // safe address; size 0 if OOB
            cp_async16(&Xs[buf][r][c4 * 4],
                       &X[(size_t)grc * K_DIM + k0 + c4 * 4],
                       (gr < N) ? 16 : 0);
        }
#pragma unroll
        for (int f = tid; f < BK * BN / 4; f += THREADS) {
            int r = f / (BN / 4), c4 = f % (BN / 4);
            cp_async16(&Ws[buf][r][c4 * 4],
                       &W[(size_t)(k0 + r) * BN + c4 * 4], 16);
        }
        asm volatile("cp.async.commit_group;");
    };

    load_stage(0, 0);

#pragma unroll
    for (int k = 0; k < NK; k++) {
        if (k + 1 < NK) load_stage((k + 1) * BK, (k + 1) & 1);
        if (k + 1 < NK) asm volatile("cp.async.wait_group 1;");
        else            asm volatile("cp.async.wait_group 0;");
        __syncthreads();

        int buf = k & 1;
#pragma unroll
        for (int kk = 0; kk < BK / 8; kk++) {
            uint32_t bf[NT][2];
#pragma unroll
            for (int nt = 0; nt < NT; nt++) {
                int col = warp_col + nt * 8 + lr;
                bf[nt][0] = f2tf32(Ws[buf][kk * 8 + lc    ][col]);
                bf[nt][1] = f2tf32(Ws[buf][kk * 8 + lc + 4][col]);
            }
#pragma unroll
            for (int mt = 0; mt < MT; mt++) {
                int rbase = warp_row + mt * 16 + lr;
                uint32_t a0 = f2tf32(Xs[buf][rbase    ][kk * 8 + lc]);
                uint32_t a1 = f2tf32(Xs[buf][rbase + 8][kk * 8 + lc]);
                uint32_t a2 = f2tf32(Xs[buf][rbase    ][kk * 8 + lc + 4]);
                uint32_t a3 = f2tf32(Xs[buf][rbase + 8][kk * 8 + lc + 4]);
#pragma unroll
                for (int nt = 0; nt < NT; nt++)
                    mma_tf32(d[mt][nt], a0, a1, a2, a3, bf[nt][0], bf[nt][1]);
            }
        }
        __syncthreads();
    }

    // --- store, scaled by dis[row], converted to fp16 pairs ---
#pragma unroll
    for (int mt = 0; mt < MT; mt++) {
        int r  = row0 + warp_row + mt * 16 + lr;
        float ds0 = (r < N)     ? g_dis[r]     : 0.f;
        float ds1 = (r + 8 < N) ? g_dis[r + 8] : 0.f;
#pragma unroll
        for (int nt = 0; nt < NT; nt++) {
            int c = warp_col + nt * 8 + 2 * lc;
            if (r < N)
                *reinterpret_cast<__half2*>(&T[(size_t)r * BN + c]) =
                    __floats2half2_rn(d[mt][nt][0] * ds0, d[mt][nt][1] * ds0);
            if (r + 8 < N)
                *reinterpret_cast<__half2*>(&T[(size_t)(r + 8) * BN + c]) =
                    __floats2half2_rn(d[mt][nt][2] * ds1, d[mt][nt][3] * ds1);
        }
    }
}

__global__ void __launch_bounds__(512)
gemm1_kernel(const float* __restrict__ X, const float* __restrict__ W) {
    gemm_db_body<128, 4, 4>(X, W, g_t1, N_NODES, blockIdx.x);   // 16 warps, 32x32 tiles
}

__global__ void __launch_bounds__(256)
gemm2_kernel(const float* __restrict__ X, const float* __restrict__ W) {
    gemm_db_body<64, 4, 2>(X, W, g_t2, N_NODES, blockIdx.x);    // 8 warps, 32x32 tiles
}

// -------- aggregate layer 1: h = relu(dis[d]*(sum t1'[src] + t1'[d]) + b1) ------
// fp16 gathers (8B per lane per edge), fp32 accumulation.
__global__ void agg1_kernel(const float* __restrict__ b1) {
    int warp = (blockIdx.x * blockDim.x + threadIdx.x) >> 5;
    int lane = threadIdx.x & 31;
    if (warp >= N_NODES) return;
    int beg = g_off[warp];
    int end = beg + g_cnt[warp];
    const uint2* T = reinterpret_cast<const uint2*>(g_t1);  // 32 uint2 (=4 half) per row

    float4 acc = make_float4(0.f, 0.f, 0.f, 0.f);
    auto accum = [&](uint2 u) {
        float2 f0 = __half22float2(*reinterpret_cast<__half2*>(&u.x));
        float2 f1 = __half22float2(*reinterpret_cast<__half2*>(&u.y));
        acc.x += f0.x; acc.y += f0.y; acc.z += f1.x; acc.w += f1.y;
    };
    int j = beg;
    for (; j + 3 < end; j += 4) {
        int s0 = g_csr_src[j],     s1 = g_csr_src[j + 1];
        int s2 = g_csr_src[j + 2], s3 = g_csr_src[j + 3];
        uint2 v0 = T[(size_t)s0 * 32 + lane];
        uint2 v1 = T[(size_t)s1 * 32 + lane];
        uint2 v2 = T[(size_t)s2 * 32 + lane];
        uint2 v3 = T[(size_t)s3 * 32 + lane];
        accum(v0); accum(v1); accum(v2); accum(v3);
    }
    for (; j < end; j++) {
        uint2 v0 = T[(size_t)g_csr_src[j] * 32 + lane];
        accum(v0);
    }
    // self term
    accum(T[(size_t)warp * 32 + lane]);

    float ds = g_dis[warp];
    float4 b = reinterpret_cast<const float4*>(b1)[lane];
    float4 r;
    r.x = fmaxf(fmaf(acc.x, ds, b.x), 0.f);
    r.y = fmaxf(fmaf(acc.y, ds, b.y), 0.f);
    r.z = fmaxf(fmaf(acc.z, ds, b.z), 0.f);
    r.w = fmaxf(fmaf(acc.w, ds, b.w), 0.f);
    reinterpret_cast<float4*>(g_h)[(size_t)warp * 32 + lane] = r;
}

// -------- aggregate layer 2: out = dis[d]*(sum t2'[src] + t2'[d]) + b2 ----------
__global__ void agg2_kernel(float* __restrict__ out, const float* __restrict__ b2) {
    int warp = (blockIdx.x * blockDim.x + threadIdx.x) >> 5;
    int lane = threadIdx.x & 31;
    if (warp >= N_NODES) return;
    int beg = g_off[warp];
    int end = beg + g_cnt[warp];
    const uint32_t* T = reinterpret_cast<const uint32_t*>(g_t2);  // 32 half2 per row

    float2 acc = make_float2(0.f, 0.f);
    auto accum = [&](uint32_t u) {
        float2 f = __half22float2(*reinterpret_cast<__half2*>(&u));
        acc.x += f.x; acc.y += f.y;
    };
    int j = beg;
    for (; j + 3 < end; j += 4) {
        int s0 = g_csr_src[j],     s1 = g_csr_src[j + 1];
        int s2 = g_csr_src[j + 2], s3 = g_csr_src[j + 3];
        uint32_t v0 = T[(size_t)s0 * 32 + lane];
        uint32_t v1 = T[(size_t)s1 * 32 + lane];
        uint32_t v2 = T[(size_t)s2 * 32 + lane];
        uint32_t v3 = T[(size_t)s3 * 32 + lane];
        accum(v0); accum(v1); accum(v2); accum(v3);
    }
    for (; j < end; j++) {
        accum(T[(size_t)g_csr_src[j] * 32 + lane]);
    }
    // self term
    accum(T[(size_t)warp * 32 + lane]);

    float ds = g_dis[warp];
    float2 b = reinterpret_cast<const float2*>(b2)[lane];
    float2 r;
    r.x = fmaf(acc.x, ds, b.x);
    r.y = fmaf(acc.y, ds, b.y);
    reinterpret_cast<float2*>(out)[(size_t)warp * 32 + lane] = r;
}

// ---------------- launcher ----------------------------------------------------
extern "C" void kernel_launch(void* const* d_in, const int* in_sizes, int n_in,
                              void* d_out, int out_size) {
    const float* x  = (const float*)d_in[0];
    const int*   ei = (const int*)d_in[1];     // int32 (JAX default) or int64 (probed)
    const float* W1 = (const float*)d_in[2];
    const float* b1 = (const float*)d_in[3];
    const float* W2 = (const float*)d_in[4];
    const float* b2 = (const float*)d_in[5];
    float* out = (float*)d_out;
    (void)in_sizes; (void)n_in; (void)out_size;

    float* hp;
    cudaGetSymbolAddress((void**)&hp, g_h);

    const int N = N_NODES, E = E_EDGES;
    const int GB = (N + 127) / 128;   // 391 GEMM blocks

    // ---- CSR build ----
    init_detect_kernel<<<(N + 255) / 256, 256>>>(ei);
    count_kernel<<<(E + 255) / 256, 256>>>(ei);
    off_dis_kernel<<<(N + 255) / 256, 256>>>();
    fill_kernel<<<(E + 255) / 256, 256>>>(ei);

    // ---- Layer 1 ----
    gemm1_kernel<<<GB, 512>>>(x, W1);
    agg1_kernel<<<(N * 32 + 255) / 256, 256>>>(b1);   // 1 warp per node

    // ---- Layer 2 ----
    gemm2_kernel<<<GB, 256>>>(hp, W2);
    agg2_kernel<<<(N * 32 + 255) / 256, 256>>>(out, b2);
}

// round 11
// speedup vs baseline: 2.2097x; 1.0238x over previous
#include <cuda_runtime.h>
#include <cuda_fp16.h>
#include <cstdint>

#define N_NODES 50000
#define E_EDGES 800000
#define K_DIM   128
#define E_HALF  (E_EDGES / 2)

// ---------------- scratch (allocation-free: __device__ globals) ----------------
__device__ __align__(16) int    g_is64;                 // edge_index dtype flag
__device__ __align__(16) int    g_total;                // CSR allocator cursor
__device__ __align__(16) int    g_cnt[N_NODES];         // in-degree (excl. self loop)
__device__ __align__(16) int    g_off[N_NODES];         // CSR row offsets
__device__ __align__(16) float  g_dis[N_NODES];         // deg^{-1/2} (incl. self loop)
__device__ __align__(16) uint32_t g_rank[E_EDGES];      // packed (dst<<16 | rank)
__device__ __align__(16) int    g_csr_src[E_EDGES];     // CSR column (source node)
__device__ __align__(16) __half g_t1[(size_t)N_NODES * 128]; // dis * (X @ W1), fp16
__device__ __align__(16) float  g_h [(size_t)N_NODES * 128]; // layer-1 output (fp32)
__device__ __align__(16) __half g_t2[(size_t)N_NODES * 64];  // dis * (h @ W2), fp16

__device__ __forceinline__ int load_edge(const int* ei32, int row, int e, int is64) {
    int idx = row * E_EDGES + e;
    return is64 ? ei32[2 * idx] : ei32[idx];   // little-endian low word for int64
}

// ---------------- cp.async helpers ----------------------------------------------
__device__ __forceinline__ void cp_async16(void* smem, const void* gmem, int src_sz) {
    uint32_t s = (uint32_t)__cvta_generic_to_shared(smem);
    asm volatile("cp.async.cg.shared.global [%0], [%1], 16, %2;"
                 :: "r"(s), "l"(gmem), "r"(src_sz));
}

// rounded tf32 conversion (rna)
__device__ __forceinline__ uint32_t f2tf32(float f) {
    uint32_t u;
    asm("cvt.rna.tf32.f32 %0, %1;" : "=r"(u) : "f"(f));
    return u;
}

__device__ __forceinline__ void mma_tf32(float d[4],
                                         uint32_t a0, uint32_t a1, uint32_t a2, uint32_t a3,
                                         uint32_t b0, uint32_t b1) {
    asm volatile(
        "mma.sync.aligned.m16n8k8.row.col.f32.tf32.tf32.f32 "
        "{%0,%1,%2,%3}, {%4,%5,%6,%7}, {%8,%9}, {%0,%1,%2,%3};"
        : "+f"(d[0]), "+f"(d[1]), "+f"(d[2]), "+f"(d[3])
        : "r"(a0), "r"(a1), "r"(a2), "r"(a3), "r"(b0), "r"(b1));
}

// ------------- init counters + detect edge dtype (block 0) ----------------------
__global__ void init_detect_kernel(const int* __restrict__ ei32) {
    int i = blockIdx.x * blockDim.x + threadIdx.x;
    if (i < N_NODES) g_cnt[i] = 0;
    if (i == 0) g_total = 0;
    if (blockIdx.x == 0) {
        __shared__ int any_nz;
        if (threadIdx.x == 0) any_nz = 0;
        __syncthreads();
        if (ei32[2 * threadIdx.x + 1] != 0) atomicOr(&any_nz, 1);
        __syncthreads();
        if (threadIdx.x == 0) g_is64 = (any_nz == 0);
    }
}

// -------- histogram: 2 edges/thread; pack (dst,rank) for the fill pass ----------
__global__ void count_kernel(const int* __restrict__ ei32) {
    int t = blockIdx.x * blockDim.x + threadIdx.x;
    if (t >= E_HALF) return;
    int is64 = g_is64;
    int d0 = load_edge(ei32, 1, t,          is64);
    int d1 = load_edge(ei32, 1, t + E_HALF, is64);
    int r0 = atomicAdd(&g_cnt[d0], 1);
    int r1 = atomicAdd(&g_cnt[d1], 1);
    g_rank[t]          = ((uint32_t)d0 << 16) | (uint32_t)r0;
    g_rank[t + E_HALF] = ((uint32_t)d1 << 16) | (uint32_t)r1;
}

// ------- offsets via warp-aggregated atomic allocator + dis ---------------------
__global__ void off_dis_kernel() {
    int i = blockIdx.x * blockDim.x + threadIdx.x;
    int lane = threadIdx.x & 31;
    int c = (i < N_NODES) ? g_cnt[i] : 0;
    int pre = c;
#pragma unroll
    for (int o = 1; o < 32; o <<= 1) {
        int v = __shfl_up_sync(0xffffffffu, pre, o);
        if (lane >= o) pre += v;
    }
    int wsum = __shfl_sync(0xffffffffu, pre, 31);
    int base = 0;
    if (lane == 31 && wsum > 0) base = atomicAdd(&g_total, wsum);
    base = __shfl_sync(0xffffffffu, base, 31);
    if (i < N_NODES) {
        g_off[i] = base + pre - c;
        g_dis[i] = rsqrtf((float)(c + 1));
    }
}

// ------- CSR fill: atomic-free, 2 edges/thread, packed (dst,rank) ---------------
__global__ void fill_kernel(const int* __restrict__ ei32) {
    int t = blockIdx.x * blockDim.x + threadIdx.x;
    if (t >= E_HALF) return;
    int is64 = g_is64;
    int s0 = load_edge(ei32, 0, t,          is64);
    int s1 = load_edge(ei32, 0, t + E_HALF, is64);
    uint32_t p0 = g_rank[t];
    uint32_t p1 = g_rank[t + E_HALF];
    g_csr_src[g_off[p0 >> 16] + (p0 & 0xFFFFu)] = s0;
    g_csr_src[g_off[p1 >> 16] + (p1 & 0xFFFFu)] = s1;
}

// -------- tf32 GEMM, cp.async double-buffered, dis-prescaled fp16 output --------
template <int BN, int WARPS_M, int WARPS_N>
__device__ __forceinline__ void gemm_db_body(const float* __restrict__ X,
                                             const float* __restrict__ W,
                                             __half* __restrict__ T, int N, int bx) {
    constexpr int BM = 128, BK = 16, NK = K_DIM / BK;
    constexpr int THREADS = WARPS_M * WARPS_N * 32;
    constexpr int WM = BM / WARPS_M, WN = BN / WARPS_N;
    constexpr int MT = WM / 16, NT = WN / 8;
    constexpr int XST = BK + 4;
    constexpr int WST = BN + 8;

    __shared__ float Xs[2][BM][XST];
    __shared__ float Ws[2][BK][WST];

    int tid  = threadIdx.x;
    int wid  = tid >> 5;
    int lane = tid & 31;
    int wm = wid / WARPS_N, wn = wid % WARPS_N;
    int warp_row = wm * WM;
    int warp_col = wn * WN;
    int row0 = bx * BM;
    int lr = lane >> 2;
    int lc = lane & 3;

    float d[MT][NT][4];
#pragma unroll
    for (int i = 0; i < MT; i++)
#pragma unroll
        for (int j = 0; j < NT; j++)
#pragma unroll
            for (int q = 0; q < 4; q++) d[i][j][q] = 0.f;

    auto load_stage = [&](int k0, int buf) {
#pragma unroll
        for (int f = tid; f < BM * BK / 4; f += THREADS) {
            int r = f / (BK / 4), c4 = f % (BK / 4);
            int gr = row0 + r;
            int grc = (gr < N) ? gr : (N - 1);
            cp_async16(&Xs[buf][r][c4 * 4],
                       &X[(size_t)grc * K_DIM + k0 + c4 * 4],
                       (gr < N) ? 16 : 0);
        }
#pragma unroll
        for (int f = tid; f < BK * BN / 4; f += THREADS) {
            int r = f / (BN / 4), c4 = f % (BN / 4);
            cp_async16(&Ws[buf][r][c4 * 4],
                       &W[(size_t)(k0 + r) * BN + c4 * 4], 16);
        }
        asm volatile("cp.async.commit_group;");
    };

    load_stage(0, 0);

#pragma unroll
    for (int k = 0; k < NK; k++) {
        if (k + 1 < NK) load_stage((k + 1) * BK, (k + 1) & 1);
        if (k + 1 < NK) asm volatile("cp.async.wait_group 1;");
        else            asm volatile("cp.async.wait_group 0;");
        __syncthreads();

        int buf = k & 1;
#pragma unroll
        for (int kk = 0; kk < BK / 8; kk++) {
            uint32_t bf[NT][2];
#pragma unroll
            for (int nt = 0; nt < NT; nt++) {
                int col = warp_col + nt * 8 + lr;
                bf[nt][0] = f2tf32(Ws[buf][kk * 8 + lc    ][col]);
                bf[nt][1] = f2tf32(Ws[buf][kk * 8 + lc + 4][col]);
            }
#pragma unroll
            for (int mt = 0; mt < MT; mt++) {
                int rbase = warp_row + mt * 16 + lr;
                uint32_t a0 = f2tf32(Xs[buf][rbase    ][kk * 8 + lc]);
                uint32_t a1 = f2tf32(Xs[buf][rbase + 8][kk * 8 + lc]);
                uint32_t a2 = f2tf32(Xs[buf][rbase    ][kk * 8 + lc + 4]);
                uint32_t a3 = f2tf32(Xs[buf][rbase + 8][kk * 8 + lc + 4]);
#pragma unroll
                for (int nt = 0; nt < NT; nt++)
                    mma_tf32(d[mt][nt], a0, a1, a2, a3, bf[nt][0], bf[nt][1]);
            }
        }
        __syncthreads();
    }

#pragma unroll
    for (int mt = 0; mt < MT; mt++) {
        int r  = row0 + warp_row + mt * 16 + lr;
        float ds0 = (r < N)     ? g_dis[r]     : 0.f;
        float ds1 = (r + 8 < N) ? g_dis[r + 8] : 0.f;
#pragma unroll
        for (int nt = 0; nt < NT; nt++) {
            int c = warp_col + nt * 8 + 2 * lc;
            if (r < N)
                *reinterpret_cast<__half2*>(&T[(size_t)r * BN + c]) =
                    __floats2half2_rn(d[mt][nt][0] * ds0, d[mt][nt][1] * ds0);
            if (r + 8 < N)
                *reinterpret_cast<__half2*>(&T[(size_t)(r + 8) * BN + c]) =
                    __floats2half2_rn(d[mt][nt][2] * ds1, d[mt][nt][3] * ds1);
        }
    }
}

__global__ void __launch_bounds__(512)
gemm1_kernel(const float* __restrict__ X, const float* __restrict__ W) {
    gemm_db_body<128, 4, 4>(X, W, g_t1, N_NODES, blockIdx.x);
}

__global__ void __launch_bounds__(256)
gemm2_kernel(const float* __restrict__ X, const float* __restrict__ W) {
    gemm_db_body<64, 4, 2>(X, W, g_t2, N_NODES, blockIdx.x);
}

// -------- aggregate layer 1: h = relu(dis[d]*(sum t1'[src] + t1'[d]) + b1) ------
__global__ void agg1_kernel(const float* __restrict__ b1) {
    int warp = (blockIdx.x * blockDim.x + threadIdx.x) >> 5;
    int lane = threadIdx.x & 31;
    if (warp >= N_NODES) return;
    int beg = g_off[warp];
    int end = beg + g_cnt[warp];
    const uint2* T = reinterpret_cast<const uint2*>(g_t1);

    float4 acc = make_float4(0.f, 0.f, 0.f, 0.f);
    auto accum = [&](uint2 u) {
        float2 f0 = __half22float2(*reinterpret_cast<__half2*>(&u.x));
        float2 f1 = __half22float2(*reinterpret_cast<__half2*>(&u.y));
        acc.x += f0.x; acc.y += f0.y; acc.z += f1.x; acc.w += f1.y;
    };
    int j = beg;
    for (; j + 3 < end; j += 4) {
        int s0 = g_csr_src[j],     s1 = g_csr_src[j + 1];
        int s2 = g_csr_src[j + 2], s3 = g_csr_src[j + 3];
        uint2 v0 = T[(size_t)s0 * 32 + lane];
        uint2 v1 = T[(size_t)s1 * 32 + lane];
        uint2 v2 = T[(size_t)s2 * 32 + lane];
        uint2 v3 = T[(size_t)s3 * 32 + lane];
        accum(v0); accum(v1); accum(v2); accum(v3);
    }
    for (; j < end; j++) accum(T[(size_t)g_csr_src[j] * 32 + lane]);
    accum(T[(size_t)warp * 32 + lane]);   // self term

    float ds = g_dis[warp];
    float4 b = reinterpret_cast<const float4*>(b1)[lane];
    float4 r;
    r.x = fmaxf(fmaf(acc.x, ds, b.x), 0.f);
    r.y = fmaxf(fmaf(acc.y, ds, b.y), 0.f);
    r.z = fmaxf(fmaf(acc.z, ds, b.z), 0.f);
    r.w = fmaxf(fmaf(acc.w, ds, b.w), 0.f);
    reinterpret_cast<float4*>(g_h)[(size_t)warp * 32 + lane] = r;
}

// -------- aggregate layer 2: out = dis[d]*(sum t2'[src] + t2'[d]) + b2 ----------
__global__ void agg2_kernel(float* __restrict__ out, const float* __restrict__ b2) {
    int warp = (blockIdx.x * blockDim.x + threadIdx.x) >> 5;
    int lane = threadIdx.x & 31;
    if (warp >= N_NODES) return;
    int beg = g_off[warp];
    int end = beg + g_cnt[warp];
    const uint32_t* T = reinterpret_cast<const uint32_t*>(g_t2);

    float2 acc = make_float2(0.f, 0.f);
    auto accum = [&](uint32_t u) {
        float2 f = __half22float2(*reinterpret_cast<__half2*>(&u));
        acc.x += f.x; acc.y += f.y;
    };
    int j = beg;
    for (; j + 3 < end; j += 4) {
        int s0 = g_csr_src[j],     s1 = g_csr_src[j + 1];
        int s2 = g_csr_src[j + 2], s3 = g_csr_src[j + 3];
        uint32_t v0 = T[(size_t)s0 * 32 + lane];
        uint32_t v1 = T[(size_t)s1 * 32 + lane];
        uint32_t v2 = T[(size_t)s2 * 32 + lane];
        uint32_t v3 = T[(size_t)s3 * 32 + lane];
        accum(v0); accum(v1); accum(v2); accum(v3);
    }
    for (; j < end; j++) accum(T[(size_t)g_csr_src[j] * 32 + lane]);
    accum(T[(size_t)warp * 32 + lane]);   // self term

    float ds = g_dis[warp];
    float2 b = reinterpret_cast<const float2*>(b2)[lane];
    float2 r;
    r.x = fmaf(acc.x, ds, b.x);
    r.y = fmaf(acc.y, ds, b.y);
    reinterpret_cast<float2*>(out)[(size_t)warp * 32 + lane] = r;
}

// ---------------- launcher ----------------------------------------------------
extern "C" void kernel_launch(void* const* d_in, const int* in_sizes, int n_in,
                              void* d_out, int out_size) {
    const float* x  = (const float*)d_in[0];
    const int*   ei = (const int*)d_in[1];     // int32 (JAX default) or int64 (probed)
    const float* W1 = (const float*)d_in[2];
    const float* b1 = (const float*)d_in[3];
    const float* W2 = (const float*)d_in[4];
    const float* b2 = (const float*)d_in[5];
    float* out = (float*)d_out;
    (void)in_sizes; (void)n_in; (void)out_size;

    float* hp;
    cudaGetSymbolAddress((void**)&hp, g_h);

    // one-time side-stream + events (host-side objects, no device memory)
    static cudaStream_t s_b = nullptr;
    static cudaEvent_t  ev_csr = nullptr, ev_fill = nullptr;
    if (s_b == nullptr) {
        cudaStreamCreateWithFlags(&s_b, cudaStreamNonBlocking);
        cudaEventCreateWithFlags(&ev_csr,  cudaEventDisableTiming);
        cudaEventCreateWithFlags(&ev_fill, cudaEventDisableTiming);
    }

    const int N = N_NODES;
    const int GB = (N + 127) / 128;   // 391 GEMM blocks

    // ---- CSR build prefix (default stream) ----
    init_detect_kernel<<<(N + 255) / 256, 256>>>(ei);
    count_kernel<<<(E_HALF + 255) / 256, 256>>>(ei);
    off_dis_kernel<<<(N + 255) / 256, 256>>>();

    // ---- fork: fill on side stream, gemm1 on default (independent) ----
    cudaEventRecord(ev_csr, 0);
    cudaStreamWaitEvent(s_b, ev_csr, 0);
    fill_kernel<<<(E_HALF + 255) / 256, 256, 0, s_b>>>(ei);
    cudaEventRecord(ev_fill, s_b);

    gemm1_kernel<<<GB, 512>>>(x, W1);

    // ---- join: agg1 needs both gemm1 (default) and fill (s_b) ----
    cudaStreamWaitEvent(0, ev_fill, 0);
    agg1_kernel<<<(N * 32 + 255) / 256, 256>>>(b1);

    // ---- Layer 2 (default stream) ----
    gemm2_kernel<<<GB, 256>>>(hp, W2);
    agg2_kernel<<<(N * 32 + 255) / 256, 256>>>(out, b2);
}

// round 12
// speedup vs baseline: 2.2237x; 1.0063x over previous
#include <cuda_runtime.h>
#include <cuda_fp16.h>
#include <cstdint>

#define N_NODES 50000
#define E_EDGES 800000
#define K_DIM   128
#define E_Q     (E_EDGES / 4)

// ---------------- scratch (allocation-free: __device__ globals) ----------------
// g_cnt/g_total are re-zeroed by agg2's tail each run (self-cleaning graph);
// module-load zero-init covers the very first execution.
__device__ __align__(16) int    g_is64;                 // edge_index dtype flag
__device__ __align__(16) int    g_total;                // CSR allocator cursor
__device__ __align__(16) int    g_cnt[N_NODES];         // in-degree (excl. self loop)
__device__ __align__(16) int    g_off[N_NODES];         // CSR row offsets
__device__ __align__(16) float  g_dis[N_NODES];         // deg^{-1/2} (incl. self loop)
__device__ __align__(16) uint32_t g_rank[E_EDGES];      // packed (dst<<16 | rank)
__device__ __align__(16) int    g_csr_src[E_EDGES];     // CSR column (source node)
__device__ __align__(16) __half g_t1[(size_t)N_NODES * 128]; // X @ W1 (UNSCALED, fp16)
__device__ __align__(16) float  g_h [(size_t)N_NODES * 128]; // layer-1 output (fp32)
__device__ __align__(16) __half g_t2[(size_t)N_NODES * 64];  // dis * (h @ W2), fp16

__device__ __forceinline__ int load_edge(const int* ei32, int row, int e, int is64) {
    int idx = row * E_EDGES + e;
    return is64 ? ei32[2 * idx] : ei32[idx];   // little-endian low word for int64
}

// ---------------- cp.async helpers ----------------------------------------------
__device__ __forceinline__ void cp_async16(void* smem, const void* gmem, int src_sz) {
    uint32_t s = (uint32_t)__cvta_generic_to_shared(smem);
    asm volatile("cp.async.cg.shared.global [%0], [%1], 16, %2;"
                 :: "r"(s), "l"(gmem), "r"(src_sz));
}

// rounded tf32 conversion (rna)
__device__ __forceinline__ uint32_t f2tf32(float f) {
    uint32_t u;
    asm("cvt.rna.tf32.f32 %0, %1;" : "=r"(u) : "f"(f));
    return u;
}

__device__ __forceinline__ void mma_tf32(float d[4],
                                         uint32_t a0, uint32_t a1, uint32_t a2, uint32_t a3,
                                         uint32_t b0, uint32_t b1) {
    asm volatile(
        "mma.sync.aligned.m16n8k8.row.col.f32.tf32.tf32.f32 "
        "{%0,%1,%2,%3}, {%4,%5,%6,%7}, {%8,%9}, {%0,%1,%2,%3};"
        : "+f"(d[0]), "+f"(d[1]), "+f"(d[2]), "+f"(d[3])
        : "r"(a0), "r"(a1), "r"(a2), "r"(a3), "r"(b0), "r"(b1));
}

// ---------------- detect edge dtype (1 block) ------------------------------------
__global__ void detect_kernel(const int* __restrict__ ei32) {
    __shared__ int any_nz;
    if (threadIdx.x == 0) any_nz = 0;
    __syncthreads();
    if (ei32[2 * threadIdx.x + 1] != 0) atomicOr(&any_nz, 1);
    __syncthreads();
    if (threadIdx.x == 0) g_is64 = (any_nz == 0);
}

// -------- histogram: 4 edges/thread; pack (dst,rank) for the fill pass ----------
__global__ void count_kernel(const int* __restrict__ ei32) {
    int t = blockIdx.x * blockDim.x + threadIdx.x;
    if (t >= E_Q) return;
    int is64 = g_is64;
#pragma unroll
    for (int q = 0; q < 4; q++) {
        int e = t + q * E_Q;
        int d = load_edge(ei32, 1, e, is64);
        int r = atomicAdd(&g_cnt[d], 1);
        g_rank[e] = ((uint32_t)d << 16) | (uint32_t)r;
    }
}

// ------- offsets via warp-aggregated atomic allocator + dis ---------------------
__global__ void off_dis_kernel() {
    int i = blockIdx.x * blockDim.x + threadIdx.x;
    int lane = threadIdx.x & 31;
    int c = (i < N_NODES) ? g_cnt[i] : 0;
    int pre = c;
#pragma unroll
    for (int o = 1; o < 32; o <<= 1) {
        int v = __shfl_up_sync(0xffffffffu, pre, o);
        if (lane >= o) pre += v;
    }
    int wsum = __shfl_sync(0xffffffffu, pre, 31);
    int base = 0;
    if (lane == 31 && wsum > 0) base = atomicAdd(&g_total, wsum);
    base = __shfl_sync(0xffffffffu, base, 31);
    if (i < N_NODES) {
        g_off[i] = base + pre - c;
        g_dis[i] = rsqrtf((float)(c + 1));
    }
}

// ------- CSR fill: atomic-free, 4 edges/thread, packed (dst,rank) ---------------
__global__ void fill_kernel(const int* __restrict__ ei32) {
    int t = blockIdx.x * blockDim.x + threadIdx.x;
    if (t >= E_Q) return;
    int is64 = g_is64;
#pragma unroll
    for (int q = 0; q < 4; q++) {
        int e = t + q * E_Q;
        int s = load_edge(ei32, 0, e, is64);
        uint32_t p = g_rank[e];
        g_csr_src[g_off[p >> 16] + (p & 0xFFFFu)] = s;
    }
}

// -------- tf32 GEMM, cp.async double-buffered, fp16 output ----------------------
// SCALED=0: T = X @ W (no dis dependency). SCALED=1: T = dis * (X @ W).
template <int BN, int WARPS_M, int WARPS_N, int SCALED>
__device__ __forceinline__ void gemm_db_body(const float* __restrict__ X,
                                             const float* __restrict__ W,
                                             __half* __restrict__ T, int N, int bx) {
    constexpr int BM = 128, BK = 16, NK = K_DIM / BK;
    constexpr int THREADS = WARPS_M * WARPS_N * 32;
    constexpr int WM = BM / WARPS_M, WN = BN / WARPS_N;
    constexpr int MT = WM / 16, NT = WN / 8;
    constexpr int XST = BK + 4;
    constexpr int WST = BN + 8;

    __shared__ float Xs[2][BM][XST];
    __shared__ float Ws[2][BK][WST];

    int tid  = threadIdx.x;
    int wid  = tid >> 5;
    int lane = tid & 31;
    int wm = wid / WARPS_N, wn = wid % WARPS_N;
    int warp_row = wm * WM;
    int warp_col = wn * WN;
    int row0 = bx * BM;
    int lr = lane >> 2;
    int lc = lane & 3;

    float d[MT][NT][4];
#pragma unroll
    for (int i = 0; i < MT; i++)
#pragma unroll
        for (int j = 0; j < NT; j++)
#pragma unroll
            for (int q = 0; q < 4; q++) d[i][j][q] = 0.f;

    auto load_stage = [&](int k0, int buf) {
#pragma unroll
        for (int f = tid; f < BM * BK / 4; f += THREADS) {
            int r = f / (BK / 4), c4 = f % (BK / 4);
            int gr = row0 + r;
            int grc = (gr < N) ? gr : (N - 1);
            cp_async16(&Xs[buf][r][c4 * 4],
                       &X[(size_t)grc * K_DIM + k0 + c4 * 4],
                       (gr < N) ? 16 : 0);
        }
#pragma unroll
        for (int f = tid; f < BK * BN / 4; f += THREADS) {
            int r = f / (BN / 4), c4 = f % (BN / 4);
            cp_async16(&Ws[buf][r][c4 * 4],
                       &W[(size_t)(k0 + r) * BN + c4 * 4], 16);
        }
        asm volatile("cp.async.commit_group;");
    };

    load_stage(0, 0);

#pragma unroll
    for (int k = 0; k < NK; k++) {
        if (k + 1 < NK) load_stage((k + 1) * BK, (k + 1) & 1);
        if (k + 1 < NK) asm volatile("cp.async.wait_group 1;");
        else            asm volatile("cp.async.wait_group 0;");
        __syncthreads();

        int buf = k & 1;
#pragma unroll
        for (int kk = 0; kk < BK / 8; kk++) {
            uint32_t bf[NT][2];
#pragma unroll
            for (int nt = 0; nt < NT; nt++) {
                int col = warp_col + nt * 8 + lr;
                bf[nt][0] = f2tf32(Ws[buf][kk * 8 + lc    ][col]);
                bf[nt][1] = f2tf32(Ws[buf][kk * 8 + lc + 4][col]);
            }
#pragma unroll
            for (int mt = 0; mt < MT; mt++) {
                int rbase = warp_row + mt * 16 + lr;
                uint32_t a0 = f2tf32(Xs[buf][rbase    ][kk * 8 + lc]);
                uint32_t a1 = f2tf32(Xs[buf][rbase + 8][kk * 8 + lc]);
                uint32_t a2 = f2tf32(Xs[buf][rbase    ][kk * 8 + lc + 4]);
                uint32_t a3 = f2tf32(Xs[buf][rbase + 8][kk * 8 + lc + 4]);
#pragma unroll
                for (int nt = 0; nt < NT; nt++)
                    mma_tf32(d[mt][nt], a0, a1, a2, a3, bf[nt][0], bf[nt][1]);
            }
        }
        __syncthreads();
    }

#pragma unroll
    for (int mt = 0; mt < MT; mt++) {
        int r  = row0 + warp_row + mt * 16 + lr;
        float ds0 = 1.f, ds1 = 1.f;
        if (SCALED) {
            ds0 = (r < N)     ? g_dis[r]     : 0.f;
            ds1 = (r + 8 < N) ? g_dis[r + 8] : 0.f;
        }
#pragma unroll
        for (int nt = 0; nt < NT; nt++) {
            int c = warp_col + nt * 8 + 2 * lc;
            if (r < N)
                *reinterpret_cast<__half2*>(&T[(size_t)r * BN + c]) =
                    __floats2half2_rn(d[mt][nt][0] * ds0, d[mt][nt][1] * ds0);
            if (r + 8 < N)
                *reinterpret_cast<__half2*>(&T[(size_t)(r + 8) * BN + c]) =
                    __floats2half2_rn(d[mt][nt][2] * ds1, d[mt][nt][3] * ds1);
        }
    }
}

__global__ void __launch_bounds__(512)
gemm1_kernel(const float* __restrict__ X, const float* __restrict__ W) {
    gemm_db_body<128, 4, 4, 0>(X, W, g_t1, N_NODES, blockIdx.x);  // unscaled
}

__global__ void __launch_bounds__(256)
gemm2_kernel(const float* __restrict__ X, const float* __restrict__ W) {
    gemm_db_body<64, 4, 2, 1>(X, W, g_t2, N_NODES, blockIdx.x);   // dis-prescaled
}

// ---- aggregate layer 1: h = relu(dis[d]*(sum dis[s]*t1[s] + dis[d]*t1[d]) + b1) -
__global__ void agg1_kernel(const float* __restrict__ b1) {
    int warp = (blockIdx.x * blockDim.x + threadIdx.x) >> 5;
    int lane = threadIdx.x & 31;
    if (warp >= N_NODES) return;
    int beg = g_off[warp];
    int end = beg + g_cnt[warp];
    const uint2* T = reinterpret_cast<const uint2*>(g_t1);

    float4 acc = make_float4(0.f, 0.f, 0.f, 0.f);
    auto accumw = [&](uint2 u, float w) {
        float2 f0 = __half22float2(*reinterpret_cast<__half2*>(&u.x));
        float2 f1 = __half22float2(*reinterpret_cast<__half2*>(&u.y));
        acc.x = fmaf(f0.x, w, acc.x); acc.y = fmaf(f0.y, w, acc.y);
        acc.z = fmaf(f1.x, w, acc.z); acc.w = fmaf(f1.y, w, acc.w);
    };
    int j = beg;
    for (; j + 3 < end; j += 4) {
        int s0 = g_csr_src[j],     s1 = g_csr_src[j + 1];
        int s2 = g_csr_src[j + 2], s3 = g_csr_src[j + 3];
        float w0 = g_dis[s0], w1 = g_dis[s1], w2 = g_dis[s2], w3 = g_dis[s3];
        uint2 v0 = T[(size_t)s0 * 32 + lane];
        uint2 v1 = T[(size_t)s1 * 32 + lane];
        uint2 v2 = T[(size_t)s2 * 32 + lane];
        uint2 v3 = T[(size_t)s3 * 32 + lane];
        accumw(v0, w0); accumw(v1, w1); accumw(v2, w2); accumw(v3, w3);
    }
    for (; j < end; j++) {
        int s0 = g_csr_src[j];
        accumw(T[(size_t)s0 * 32 + lane], g_dis[s0]);
    }
    float ds = g_dis[warp];
    accumw(T[(size_t)warp * 32 + lane], ds);   // self term

    float4 b = reinterpret_cast<const float4*>(b1)[lane];
    float4 r;
    r.x = fmaxf(fmaf(acc.x, ds, b.x), 0.f);
    r.y = fmaxf(fmaf(acc.y, ds, b.y), 0.f);
    r.z = fmaxf(fmaf(acc.z, ds, b.z), 0.f);
    r.w = fmaxf(fmaf(acc.w, ds, b.w), 0.f);
    reinterpret_cast<float4*>(g_h)[(size_t)warp * 32 + lane] = r;
}

// -------- aggregate layer 2: out = dis[d]*(sum t2'[src] + t2'[d]) + b2 ----------
// Tail re-zeroes g_cnt/g_total for the next graph replay (self-cleaning).
__global__ void agg2_kernel(float* __restrict__ out, const float* __restrict__ b2) {
    int warp = (blockIdx.x * blockDim.x + threadIdx.x) >> 5;
    int lane = threadIdx.x & 31;
    if (warp >= N_NODES) return;
    int beg = g_off[warp];
    int end = beg + g_cnt[warp];
    const uint32_t* T = reinterpret_cast<const uint32_t*>(g_t2);

    float2 acc = make_float2(0.f, 0.f);
    auto accum = [&](uint32_t u) {
        float2 f = __half22float2(*reinterpret_cast<__half2*>(&u));
        acc.x += f.x; acc.y += f.y;
    };
    int j = beg;
    for (; j + 3 < end; j += 4) {
        int s0 = g_csr_src[j],     s1 = g_csr_src[j + 1];
        int s2 = g_csr_src[j + 2], s3 = g_csr_src[j + 3];
        uint32_t v0 = T[(size_t)s0 * 32 + lane];
        uint32_t v1 = T[(size_t)s1 * 32 + lane];
        uint32_t v2 = T[(size_t)s2 * 32 + lane];
        uint32_t v3 = T[(size_t)s3 * 32 + lane];
        accum(v0); accum(v1); accum(v2); accum(v3);
    }
    for (; j < end; j++) accum(T[(size_t)g_csr_src[j] * 32 + lane]);
    accum(T[(size_t)warp * 32 + lane]);   // self term

    float ds = g_dis[warp];
    float2 b = reinterpret_cast<const float2*>(b2)[lane];
    float2 r;
    r.x = fmaf(acc.x, ds, b.x);
    r.y = fmaf(acc.y, ds, b.y);
    reinterpret_cast<float2*>(out)[(size_t)warp * 32 + lane] = r;

    // self-clean for next replay
    if (lane == 0) g_cnt[warp] = 0;
    if (warp == 0 && lane == 0) g_total = 0;
}

// ---------------- launcher ----------------------------------------------------
extern "C" void kernel_launch(void* const* d_in, const int* in_sizes, int n_in,
                              void* d_out, int out_size) {
    const float* x  = (const float*)d_in[0];
    const int*   ei = (const int*)d_in[1];     // int32 (JAX default) or int64 (probed)
    const float* W1 = (const float*)d_in[2];
    const float* b1 = (const float*)d_in[3];
    const float* W2 = (const float*)d_in[4];
    const float* b2 = (const float*)d_in[5];
    float* out = (float*)d_out;
    (void)in_sizes; (void)n_in; (void)out_size;

    float* hp;
    cudaGetSymbolAddress((void**)&hp, g_h);

    // one-time side-stream + events (host-side objects, no device memory)
    static cudaStream_t s_b = nullptr;
    static cudaEvent_t  ev0 = nullptr, ev_csr = nullptr;
    if (s_b == nullptr) {
        cudaStreamCreateWithFlags(&s_b, cudaStreamNonBlocking);
        cudaEventCreateWithFlags(&ev0,    cudaEventDisableTiming);
        cudaEventCreateWithFlags(&ev_csr, cudaEventDisableTiming);
    }

    const int N = N_NODES;
    const int GB = (N + 127) / 128;   // 391 GEMM blocks

    // ---- fork: whole CSR chain on side stream; gemm1 (dis-independent) on default
    cudaEventRecord(ev0, 0);
    cudaStreamWaitEvent(s_b, ev0, 0);
    detect_kernel<<<1, 256, 0, s_b>>>(ei);
    count_kernel<<<(E_Q + 255) / 256, 256, 0, s_b>>>(ei);
    off_dis_kernel<<<(N + 255) / 256, 256, 0, s_b>>>();
    fill_kernel<<<(E_Q + 255) / 256, 256, 0, s_b>>>(ei);
    cudaEventRecord(ev_csr, s_b);

    gemm1_kernel<<<GB, 512>>>(x, W1);    // concurrent with CSR build

    // ---- join: agg1 needs gemm1 (default) + CSR chain (s_b) ----
    cudaStreamWaitEvent(0, ev_csr, 0);
    agg1_kernel<<<(N * 32 + 255) / 256, 256>>>(b1);

    // ---- Layer 2 (default stream) ----
    gemm2_kernel<<<GB, 256>>>(hp, W2);
    agg2_kernel<<<(N * 32 + 255) / 256, 256>>>(out, b2);
}